// round 2
// baseline (speedup 1.0000x reference)
#include <cuda_runtime.h>
#include <math.h>

// Problem constants (shapes fixed by the dataset; N,E read from in_sizes)
#define F    1024
#define MAXN 10000
#define MAXE 80000
#define NG   64
#define DD   128

// ---------------- static device scratch (no allocations allowed) ----------------
__device__ float g_agg[2][(size_t)MAXN * F];   // A_hat @ x          (40MB each)
__device__ float g_y[2][(size_t)MAXN * F];     // leaky(agg@W + b)   (40MB each)
__device__ int   g_deg[2][MAXN];
__device__ float g_dinv[2][MAXN];
__device__ int   g_rowptr[2][MAXN + 1];
__device__ int   g_cursor[2][MAXN];
__device__ int   g_col[2][MAXE];
__device__ int   g_goff[2][NG + 1];
__device__ float g_pool[2][NG * F];
__device__ float g_z[2][NG * DD];
__device__ int   g_is64[4];   // 0: edge b0, 1: batch b0, 2: edge b1, 3: batch b1

__device__ __forceinline__ float leaky(float v) { return v >= 0.0f ? v : 0.01f * v; }

// Read logical element i of an index tensor of unknown dtype (int32 vs int64).
__device__ __forceinline__ int idx_at(const void* p, long long i, int is64) {
    return is64 ? (int)(((const long long*)p)[i]) : ((const int*)p)[i];
}

// ---------------- dtype detection ----------------
// Interpret buffer as 32-bit words; OR all odd-position words over the first
// `nwords` words (== element count, so always within the buffer). For int64
// data with small values the high words are all 0; for int32 they are node
// ids / graph ids and cannot all be zero (batch tail holds 63s).
__global__ void k_detect(const unsigned int* __restrict__ p, int nwords, int slot) {
    __shared__ unsigned int sh[256];
    unsigned int acc = 0;
    for (int i = 1 + 2 * threadIdx.x; i < nwords; i += 2 * 256) acc |= p[i];
    sh[threadIdx.x] = acc;
    __syncthreads();
    for (int s = 128; s > 0; s >>= 1) {
        if (threadIdx.x < s) sh[threadIdx.x] |= sh[threadIdx.x + s];
        __syncthreads();
    }
    if (threadIdx.x == 0) g_is64[slot] = (sh[0] == 0u) ? 1 : 0;
}

// ---------------- graph preprocessing ----------------
__global__ void k_zero_deg() {
    int i = blockIdx.x * blockDim.x + threadIdx.x;
    if (i < 2 * MAXN) g_deg[i / MAXN][i % MAXN] = 0;
}

__global__ void k_deg(int b, const void* __restrict__ ei, int E, int slot) {
    int e = blockIdx.x * blockDim.x + threadIdx.x;
    if (e < E) {
        int is64 = g_is64[slot];
        int d = idx_at(ei, (long long)E + e, is64);   // dst row
        atomicAdd(&g_deg[b][d], 1);
    }
}

__global__ void k_dinv(int b, int N) {
    int i = blockIdx.x * blockDim.x + threadIdx.x;
    if (i < N) g_dinv[b][i] = rsqrtf((float)(g_deg[b][i] + 1));  // +1 self-loop
}

// single-block exclusive scan of deg -> rowptr (and cursor copy)
__global__ void k_scan(int b, int N) {
    __shared__ int sh[1024];
    __shared__ int carry;
    if (threadIdx.x == 0) carry = 0;
    __syncthreads();
    for (int base = 0; base < N; base += 1024) {
        int i = base + threadIdx.x;
        int v = (i < N) ? g_deg[b][i] : 0;
        sh[threadIdx.x] = v;
        __syncthreads();
        #pragma unroll
        for (int off = 1; off < 1024; off <<= 1) {
            int t = (threadIdx.x >= off) ? sh[threadIdx.x - off] : 0;
            __syncthreads();
            sh[threadIdx.x] += t;
            __syncthreads();
        }
        if (i < N) {
            int excl = carry + sh[threadIdx.x] - v;
            g_rowptr[b][i] = excl;
            g_cursor[b][i] = excl;
        }
        __syncthreads();
        if (threadIdx.x == 1023) carry += sh[1023];
        __syncthreads();
    }
    if (threadIdx.x == 0) g_rowptr[b][N] = carry;
}

__global__ void k_fill(int b, const void* __restrict__ ei, int E, int slot) {
    int e = blockIdx.x * blockDim.x + threadIdx.x;
    if (e < E) {
        int is64 = g_is64[slot];
        int s = idx_at(ei, e, is64);                  // src
        int d = idx_at(ei, (long long)E + e, is64);   // dst
        int pos = atomicAdd(&g_cursor[b][d], 1);
        g_col[b][pos] = s;
    }
}

// ---------------- aggregation: agg[row] = dinv[row]^2*x[row] + sum dinv[s]*dinv[row]*x[s] ----------------
__global__ void k_agg(int b, const float* __restrict__ x) {
    int row = blockIdx.x;
    int t = threadIdx.x;                       // 256 threads, 4 feats each (float4)
    const float4* __restrict__ x4 = (const float4*)x;
    float dv = g_dinv[b][row];
    float4 xr = __ldg(&x4[(size_t)row * 256 + t]);
    float w0 = dv * dv;
    float4 acc;
    acc.x = xr.x * w0; acc.y = xr.y * w0; acc.z = xr.z * w0; acc.w = xr.w * w0;
    int s = g_rowptr[b][row], e = g_rowptr[b][row + 1];
    for (int j = s; j < e; j++) {
        int u = g_col[b][j];
        float w = g_dinv[b][u] * dv;
        float4 xu = __ldg(&x4[(size_t)u * 256 + t]);
        acc.x += xu.x * w; acc.y += xu.y * w; acc.z += xu.z * w; acc.w += xu.w * w;
    }
    ((float4*)g_agg[b])[(size_t)row * 256 + t] = acc;
}

// ---------------- SGEMM: Y = leaky(agg @ W + bias), M x 1024 x 1024 ----------------
#define BM 128
#define BN 128
#define BK 16
#define TM 8
#define TN 8

__global__ __launch_bounds__(256, 2)
void k_gemm(int b, const float* __restrict__ W, const float* __restrict__ bias, int M) {
    const int K = F, NC = F;
    __shared__ float As[BK][BM];
    __shared__ float Bs[BK][BN];
    const float* __restrict__ A = g_agg[b];
    float* __restrict__ Y = g_y[b];

    int bm = blockIdx.y * BM;
    int bn = blockIdx.x * BN;
    int tid = threadIdx.x;
    int tx = tid & 15;   // column group (8 cols each)
    int ty = tid >> 4;   // row group (8 rows each)

    float acc[TM][TN];
    #pragma unroll
    for (int i = 0; i < TM; i++)
        #pragma unroll
        for (int j = 0; j < TN; j++) acc[i][j] = 0.0f;

    for (int k0 = 0; k0 < K; k0 += BK) {
        // load A tile (128 rows x 16 k), 512 float4 total -> 2 per thread, store transposed
        #pragma unroll
        for (int l = 0; l < 2; l++) {
            int idx = tid + l * 256;          // 0..511
            int r = idx >> 2;                 // 0..127
            int kk = (idx & 3) * 4;           // 0,4,8,12
            int grow = bm + r;
            float4 v = make_float4(0.f, 0.f, 0.f, 0.f);
            if (grow < M) v = *(const float4*)(A + (size_t)grow * K + k0 + kk);
            As[kk + 0][r] = v.x; As[kk + 1][r] = v.y;
            As[kk + 2][r] = v.z; As[kk + 3][r] = v.w;
        }
        // load B tile (16 k x 128 cols), 512 float4 -> 2 per thread
        #pragma unroll
        for (int l = 0; l < 2; l++) {
            int idx = tid + l * 256;
            int kk = idx >> 5;                // 0..15
            int nn = (idx & 31) * 4;          // 0..124
            float4 v = *(const float4*)(W + (size_t)(k0 + kk) * NC + bn + nn);
            *(float4*)&Bs[kk][nn] = v;
        }
        __syncthreads();
        #pragma unroll
        for (int kk = 0; kk < BK; kk++) {
            float a[TM], bb[TN];
            #pragma unroll
            for (int i = 0; i < TM; i++) a[i] = As[kk][ty * TM + i];
            #pragma unroll
            for (int j = 0; j < TN; j++) bb[j] = Bs[kk][tx * TN + j];
            #pragma unroll
            for (int i = 0; i < TM; i++)
                #pragma unroll
                for (int j = 0; j < TN; j++) acc[i][j] += a[i] * bb[j];
        }
        __syncthreads();
    }

    // epilogue: bias + leaky, vectorized store
    #pragma unroll
    for (int i = 0; i < TM; i++) {
        int grow = bm + ty * TM + i;
        if (grow >= M) continue;
        #pragma unroll
        for (int j = 0; j < TN; j += 4) {
            int gcol = bn + tx * TN + j;
            float4 v;
            v.x = leaky(acc[i][j + 0] + bias[gcol + 0]);
            v.y = leaky(acc[i][j + 1] + bias[gcol + 1]);
            v.z = leaky(acc[i][j + 2] + bias[gcol + 2]);
            v.w = leaky(acc[i][j + 3] + bias[gcol + 3]);
            *(float4*)(Y + (size_t)grow * NC + gcol) = v;
        }
    }
}

// ---------------- graph segment offsets via binary search on sorted batch ----------------
__global__ void k_goff(int b, const void* __restrict__ batch, int N, int slot) {
    int g = threadIdx.x;
    if (g > NG) return;
    int is64 = g_is64[slot];
    int lo = 0, hi = N;
    while (lo < hi) {
        int mid = (lo + hi) >> 1;
        if (idx_at(batch, mid, is64) < g) lo = mid + 1; else hi = mid;
    }
    g_goff[b][g] = lo;
}

// ---------------- global mean pool ----------------
__global__ void k_pool(int b) {
    int g = blockIdx.y;
    int c = blockIdx.x * 128 + threadIdx.x;
    int s = g_goff[b][g], e = g_goff[b][g + 1];
    float sum = 0.0f;
    for (int r = s; r < e; r++) sum += g_y[b][(size_t)r * F + c];
    float cnt = (float)(e - s);
    g_pool[b][g * F + c] = sum / fmaxf(cnt, 1.0f);
}

// ---------------- fc: z = leaky(pool @ Wf + bf), [64,1024]x[1024,128] ----------------
__global__ void k_fc(int b, const float* __restrict__ Wf, const float* __restrict__ bf) {
    __shared__ float p[F];
    int g = blockIdx.x, t = threadIdx.x;       // 128 threads
    for (int k = t; k < F; k += 128) p[k] = g_pool[b][g * F + k];
    __syncthreads();
    float acc = 0.0f;
    #pragma unroll 8
    for (int k = 0; k < F; k++) acc += p[k] * Wf[k * DD + t];
    acc += bf[t];
    g_z[b][g * DD + t] = leaky(acc);
}

// ---------------- final: out[g] = [z1|z2] . finalW + finalb ----------------
__global__ void k_final(const float* __restrict__ fW, const float* __restrict__ fb,
                        float* __restrict__ out) {
    __shared__ float sh[256];
    int g = blockIdx.x, t = threadIdx.x;
    float v;
    if (t < DD) v = g_z[0][g * DD + t] * fW[t];
    else        v = g_z[1][g * DD + (t - DD)] * fW[t];
    sh[t] = v;
    __syncthreads();
    #pragma unroll
    for (int s = 128; s > 0; s >>= 1) {
        if (t < s) sh[t] += sh[t + s];
        __syncthreads();
    }
    if (t == 0) out[g] = sh[0] + fb[0];
}

// ---------------- host launcher ----------------
extern "C" void kernel_launch(void* const* d_in, const int* in_sizes, int n_in,
                              void* d_out, int out_size) {
    // Graph inputs: fixed leading positions.
    const float* x1  = (const float*)d_in[0];
    const void*  ei1 = d_in[1];
    const void*  bt1 = d_in[2];
    const float* x2  = (const float*)d_in[3];
    const void*  ei2 = d_in[4];
    const void*  bt2 = d_in[5];
    // Weights: always the LAST 10 inputs (robust to how the scalar inputs are
    // materialized — n_in may be 16 or 20).
    int wb = n_in - 10;
    const float* c1W = (const float*)d_in[wb + 0];
    const float* c1b = (const float*)d_in[wb + 1];
    const float* f1W = (const float*)d_in[wb + 2];
    const float* f1b = (const float*)d_in[wb + 3];
    const float* c2W = (const float*)d_in[wb + 4];
    const float* c2b = (const float*)d_in[wb + 5];
    const float* f2W = (const float*)d_in[wb + 6];
    const float* f2b = (const float*)d_in[wb + 7];
    const float* fW  = (const float*)d_in[wb + 8];
    const float* fb  = (const float*)d_in[wb + 9];
    float* out = (float*)d_out;

    int N = in_sizes[0] / F;   // element counts are dtype-independent
    int E = in_sizes[1] / 2;

    const float* xs[2]  = {x1, x2};
    const void*  eis[2] = {ei1, ei2};
    const void*  bts[2] = {bt1, bt2};
    const float* cW[2]  = {c1W, c2W};
    const float* cb[2]  = {c1b, c2b};
    const float* fWb[2] = {f1W, f2W};
    const float* fbb[2] = {f1b, f2b};

    // dtype detection (int32 vs int64) for each index tensor
    k_detect<<<1, 256>>>((const unsigned int*)ei1, 2 * E, 0);
    k_detect<<<1, 256>>>((const unsigned int*)bt1, N, 1);
    k_detect<<<1, 256>>>((const unsigned int*)ei2, 2 * E, 2);
    k_detect<<<1, 256>>>((const unsigned int*)bt2, N, 3);

    k_zero_deg<<<(2 * MAXN + 255) / 256, 256>>>();

    for (int b = 0; b < 2; b++) {
        int eslot = 2 * b, bslot = 2 * b + 1;

        k_deg<<<(E + 255) / 256, 256>>>(b, eis[b], E, eslot);
        k_dinv<<<(N + 255) / 256, 256>>>(b, N);
        k_scan<<<1, 1024>>>(b, N);
        k_fill<<<(E + 255) / 256, 256>>>(b, eis[b], E, eslot);
        k_agg<<<N, 256>>>(b, xs[b]);

        dim3 ggrid(F / BN, (N + BM - 1) / BM);
        k_gemm<<<ggrid, 256>>>(b, cW[b], cb[b], N);

        k_goff<<<1, NG + 1>>>(b, bts[b], N, bslot);
        dim3 pgrid(F / 128, NG);
        k_pool<<<pgrid, 128>>>(b);
        k_fc<<<NG, DD>>>(b, fWb[b], fbb[b]);
    }

    k_final<<<NG, 256>>>(fW, fb, out);
}

// round 4
// speedup vs baseline: 1.8812x; 1.8812x over previous
#include <cuda_runtime.h>
#include <cuda_bf16.h>
#include <cstdint>
#include <math.h>

#define F    1024
#define MAXN 10000
#define MAXE 80000
#define NG   64
#define DD   128

// ---------------- static device scratch ----------------
__device__ float          g_y[(size_t)MAXN * F];       // leaky(agg@W + b) (reused per branch)
__device__ __nv_bfloat16  g_ahi[(size_t)MAXN * F];     // hi(agg)
__device__ __nv_bfloat16  g_alo[(size_t)MAXN * F];     // lo(agg)
__device__ __nv_bfloat16  g_whi[(size_t)F * F];        // W^T hi  [n][k]
__device__ __nv_bfloat16  g_wlo[(size_t)F * F];        // W^T lo  [n][k]
__device__ int   g_deg[2][MAXN];
__device__ float g_dinv[2][MAXN];
__device__ int   g_rowptr[2][MAXN + 1];
__device__ int   g_cursor[2][MAXN];
__device__ int   g_col[2][MAXE];
__device__ int   g_goff[2][NG + 1];
__device__ float g_pool[2][NG * F];
__device__ float g_z[2][NG * DD];
__device__ int   g_is64[4];

__device__ __forceinline__ float leaky(float v) { return v >= 0.0f ? v : 0.01f * v; }

__device__ __forceinline__ int idx_at(const void* p, long long i, int is64) {
    return is64 ? (int)(((const long long*)p)[i]) : ((const int*)p)[i];
}

// ---------------- low-level helpers ----------------
__device__ __forceinline__ uint32_t smem_to_u32(const void* smem_ptr) {
    uint32_t addr;
    asm("{ .reg .u64 tmp; cvta.to.shared.u64 tmp, %1; cvt.u32.u64 %0, tmp; }"
        : "=r"(addr) : "l"(smem_ptr));
    return addr;
}
__device__ __forceinline__ void cp_async16(uint32_t dst, const void* src, bool p) {
    asm volatile("cp.async.cg.shared.global [%0], [%1], 16, %2;"
                 :: "r"(dst), "l"(src), "r"(p ? 16u : 0u) : "memory");
}
__device__ __forceinline__ void cp_commit() {
    asm volatile("cp.async.commit_group;" ::: "memory");
}
template <int N>
__device__ __forceinline__ void cp_wait() {
    asm volatile("cp.async.wait_group %0;" :: "n"(N) : "memory");
}
__device__ __forceinline__ uint32_t lds32(uint32_t addr) {
    uint32_t v;
    asm volatile("ld.shared.b32 %0, [%1];" : "=r"(v) : "r"(addr));
    return v;
}
__device__ __forceinline__ void mma16816(float* c, const uint32_t* a, const uint32_t* b) {
    asm volatile(
        "mma.sync.aligned.m16n8k16.row.col.f32.bf16.bf16.f32 "
        "{%0,%1,%2,%3}, {%4,%5,%6,%7}, {%8,%9}, {%0,%1,%2,%3};"
        : "+f"(c[0]), "+f"(c[1]), "+f"(c[2]), "+f"(c[3])
        : "r"(a[0]), "r"(a[1]), "r"(a[2]), "r"(a[3]), "r"(b[0]), "r"(b[1]));
}

// ---------------- dtype detection (int32 vs int64 index tensors) ----------------
__global__ void k_detect(const unsigned int* __restrict__ p, int nwords, int slot) {
    __shared__ unsigned int sh[256];
    unsigned int acc = 0;
    for (int i = 1 + 2 * threadIdx.x; i < nwords; i += 2 * 256) acc |= p[i];
    sh[threadIdx.x] = acc;
    __syncthreads();
    for (int s = 128; s > 0; s >>= 1) {
        if (threadIdx.x < s) sh[threadIdx.x] |= sh[threadIdx.x + s];
        __syncthreads();
    }
    if (threadIdx.x == 0) g_is64[slot] = (sh[0] == 0u) ? 1 : 0;
}

// ---------------- graph preprocessing ----------------
__global__ void k_zero_deg() {
    int i = blockIdx.x * blockDim.x + threadIdx.x;
    if (i < 2 * MAXN) g_deg[i / MAXN][i % MAXN] = 0;
}
__global__ void k_deg(int b, const void* __restrict__ ei, int E, int slot) {
    int e = blockIdx.x * blockDim.x + threadIdx.x;
    if (e < E) {
        int is64 = g_is64[slot];
        atomicAdd(&g_deg[b][idx_at(ei, (long long)E + e, is64)], 1);
    }
}
__global__ void k_dinv(int b, int N) {
    int i = blockIdx.x * blockDim.x + threadIdx.x;
    if (i < N) g_dinv[b][i] = rsqrtf((float)(g_deg[b][i] + 1));
}
__global__ void k_scan(int b, int N) {
    __shared__ int sh[1024];
    __shared__ int carry;
    if (threadIdx.x == 0) carry = 0;
    __syncthreads();
    for (int base = 0; base < N; base += 1024) {
        int i = base + threadIdx.x;
        int v = (i < N) ? g_deg[b][i] : 0;
        sh[threadIdx.x] = v;
        __syncthreads();
        #pragma unroll
        for (int off = 1; off < 1024; off <<= 1) {
            int t = (threadIdx.x >= off) ? sh[threadIdx.x - off] : 0;
            __syncthreads();
            sh[threadIdx.x] += t;
            __syncthreads();
        }
        if (i < N) {
            int excl = carry + sh[threadIdx.x] - v;
            g_rowptr[b][i] = excl;
            g_cursor[b][i] = excl;
        }
        __syncthreads();
        if (threadIdx.x == 1023) carry += sh[1023];
        __syncthreads();
    }
    if (threadIdx.x == 0) g_rowptr[b][N] = carry;
}
__global__ void k_fill(int b, const void* __restrict__ ei, int E, int slot) {
    int e = blockIdx.x * blockDim.x + threadIdx.x;
    if (e < E) {
        int is64 = g_is64[slot];
        int s = idx_at(ei, e, is64);
        int d = idx_at(ei, (long long)E + e, is64);
        int pos = atomicAdd(&g_cursor[b][d], 1);
        g_col[b][pos] = s;
    }
}

// ---------------- aggregation (writes bf16 hi/lo split directly) ----------------
__global__ void k_agg(int b, const float* __restrict__ x) {
    int row = blockIdx.x;
    int t = threadIdx.x;                       // 256 threads, float4 each
    const float4* __restrict__ x4 = (const float4*)x;
    float dv = g_dinv[b][row];
    float4 xr = __ldg(&x4[(size_t)row * 256 + t]);
    float w0 = dv * dv;
    float4 acc;
    acc.x = xr.x * w0; acc.y = xr.y * w0; acc.z = xr.z * w0; acc.w = xr.w * w0;
    int s = g_rowptr[b][row], e = g_rowptr[b][row + 1];
    for (int j = s; j < e; j++) {
        int u = g_col[b][j];
        float w = g_dinv[b][u] * dv;
        float4 xu = __ldg(&x4[(size_t)u * 256 + t]);
        acc.x += xu.x * w; acc.y += xu.y * w; acc.z += xu.z * w; acc.w += xu.w * w;
    }
    __nv_bfloat16 h0 = __float2bfloat16(acc.x), h1 = __float2bfloat16(acc.y);
    __nv_bfloat16 h2 = __float2bfloat16(acc.z), h3 = __float2bfloat16(acc.w);
    __nv_bfloat16 l0 = __float2bfloat16(acc.x - __bfloat162float(h0));
    __nv_bfloat16 l1 = __float2bfloat16(acc.y - __bfloat162float(h1));
    __nv_bfloat16 l2 = __float2bfloat16(acc.z - __bfloat162float(h2));
    __nv_bfloat16 l3 = __float2bfloat16(acc.w - __bfloat162float(h3));
    __nv_bfloat162 hp0 = {h0, h1}, hp1 = {h2, h3}, lp0 = {l0, l1}, lp1 = {l2, l3};
    uint2 hv, lv;
    hv.x = *(uint32_t*)&hp0; hv.y = *(uint32_t*)&hp1;
    lv.x = *(uint32_t*)&lp0; lv.y = *(uint32_t*)&lp1;
    ((uint2*)g_ahi)[(size_t)row * 256 + t] = hv;
    ((uint2*)g_alo)[(size_t)row * 256 + t] = lv;
}

// ---------------- W transpose + split: g_w{hi,lo}[n][k] = split(W[k][n]) ----------------
__global__ void k_wsplit(const float* __restrict__ W) {
    __shared__ float t[32][33];
    int tx = threadIdx.x, ty = threadIdx.y;
    int x = blockIdx.x * 32 + tx;
    #pragma unroll
    for (int j = 0; j < 4; j++) {
        int y = blockIdx.y * 32 + ty + j * 8;
        t[ty + j * 8][tx] = W[(size_t)y * F + x];
    }
    __syncthreads();
    int xo = blockIdx.y * 32 + tx;  // k
    #pragma unroll
    for (int j = 0; j < 4; j++) {
        int yo = blockIdx.x * 32 + ty + j * 8;  // n
        float v = t[tx][ty + j * 8];
        __nv_bfloat16 h = __float2bfloat16(v);
        __nv_bfloat16 l = __float2bfloat16(v - __bfloat162float(h));
        g_whi[(size_t)yo * F + xo] = h;
        g_wlo[(size_t)yo * F + xo] = l;
    }
}

// ---------------- split-bf16 HMMA GEMM: Y = leaky(A@W + bias) ----------------
// CTA tile 128x128, K chunk 32, 2-stage cp.async double buffer.
// 8 warps: warp_m = wid&1 (64 rows), warp_n = wid>>1 (32 cols).
#define BK       32
#define NCHUNK   (F / BK)          // 32
#define ROWPAD   40                 // bf16 elems per smem row (32 data + 8 pad)
#define SA_BYTES (128 * ROWPAD * 2) // 10240 per tensor
#define STG_BYTES (4 * SA_BYTES)    // ahi, alo, bhi, blo
#define SM_TOT   (2 * STG_BYTES)    // 81920

__global__ __launch_bounds__(256)
void k_tgemm(const float* __restrict__ bias, int M) {
    extern __shared__ char smem[];
    uint32_t sb = smem_to_u32(smem);
    int tid = threadIdx.x;
    int wid = tid >> 5, lane = tid & 31;
    int gid = lane >> 2, tig = lane & 3;
    int warp_m = wid & 1, warp_n = wid >> 1;
    int m0 = blockIdx.y * 128;
    int n0 = blockIdx.x * 128;

    float acc[4][4][4];
    #pragma unroll
    for (int i = 0; i < 4; i++)
        #pragma unroll
        for (int j = 0; j < 4; j++)
            #pragma unroll
            for (int q = 0; q < 4; q++) acc[i][j][q] = 0.0f;

    // ---- loader: one chunk into stage s ----
    auto load_chunk = [&](int c, int s) {
        uint32_t stg = sb + s * STG_BYTES;
        int k0 = c * BK;
        #pragma unroll
        for (int l = 0; l < 8; l++) {
            int idx = l * 256 + tid;
            int tsr = idx >> 9;        // 0 ahi, 1 alo, 2 bhi, 3 blo
            int rem = idx & 511;
            int row = rem >> 2;
            int c16 = rem & 3;
            const __nv_bfloat16* gsrc;
            bool pred = true;
            if (tsr < 2) {
                int grow = m0 + row;
                pred = grow < M;
                const __nv_bfloat16* base = (tsr == 0) ? g_ahi : g_alo;
                gsrc = base + (size_t)(pred ? grow : 0) * F + k0 + c16 * 8;
            } else {
                const __nv_bfloat16* base = (tsr == 2) ? g_whi : g_wlo;
                gsrc = base + (size_t)(n0 + row) * F + k0 + c16 * 8;
            }
            uint32_t sdst = stg + tsr * SA_BYTES + row * (ROWPAD * 2) + c16 * 16;
            cp_async16(sdst, gsrc, pred);
        }
        cp_commit();
    };

    load_chunk(0, 0);

    for (int c = 0; c < NCHUNK; c++) {
        int s = c & 1;
        if (c + 1 < NCHUNK) {
            load_chunk(c + 1, s ^ 1);
            cp_wait<1>();
        } else {
            cp_wait<0>();
        }
        __syncthreads();

        uint32_t sa = sb + s * STG_BYTES;                 // ahi
        uint32_t sbm = sb + s * STG_BYTES + 2 * SA_BYTES; // bhi

        #pragma unroll
        for (int ks = 0; ks < 2; ks++) {
            int kb = ks * 16;
            uint32_t bh[4][2], bl[4][2];
            #pragma unroll
            for (int nt = 0; nt < 4; nt++) {
                int n = warp_n * 32 + nt * 8 + gid;
                uint32_t o = n * (ROWPAD * 2) + (kb + tig * 2) * 2;
                bh[nt][0] = lds32(sbm + o);
                bh[nt][1] = lds32(sbm + o + 16);
                bl[nt][0] = lds32(sbm + SA_BYTES + o);
                bl[nt][1] = lds32(sbm + SA_BYTES + o + 16);
            }
            #pragma unroll
            for (int mt = 0; mt < 4; mt++) {
                int r = warp_m * 64 + mt * 16 + gid;
                uint32_t o = r * (ROWPAD * 2) + (kb + tig * 2) * 2;
                uint32_t ah[4], al[4];
                ah[0] = lds32(sa + o);
                ah[1] = lds32(sa + o + 8 * (ROWPAD * 2));
                ah[2] = lds32(sa + o + 16);
                ah[3] = lds32(sa + o + 8 * (ROWPAD * 2) + 16);
                al[0] = lds32(sa + SA_BYTES + o);
                al[1] = lds32(sa + SA_BYTES + o + 8 * (ROWPAD * 2));
                al[2] = lds32(sa + SA_BYTES + o + 16);
                al[3] = lds32(sa + SA_BYTES + o + 8 * (ROWPAD * 2) + 16);
                #pragma unroll
                for (int nt = 0; nt < 4; nt++) {
                    mma16816(acc[mt][nt], ah, bh[nt]);
                    mma16816(acc[mt][nt], ah, bl[nt]);
                    mma16816(acc[mt][nt], al, bh[nt]);
                }
            }
        }
        __syncthreads();
    }

    // ---- epilogue: bias + leaky, store fp32 ----
    #pragma unroll
    for (int mt = 0; mt < 4; mt++) {
        int r0 = m0 + warp_m * 64 + mt * 16 + gid;
        #pragma unroll
        for (int nt = 0; nt < 4; nt++) {
            int col = n0 + warp_n * 32 + nt * 8 + tig * 2;
            float b0 = __ldg(&bias[col]);
            float b1 = __ldg(&bias[col + 1]);
            float* cf = acc[mt][nt];
            if (r0 < M) {
                float2 v = {leaky(cf[0] + b0), leaky(cf[1] + b1)};
                *(float2*)(g_y + (size_t)r0 * F + col) = v;
            }
            if (r0 + 8 < M) {
                float2 v = {leaky(cf[2] + b0), leaky(cf[3] + b1)};
                *(float2*)(g_y + (size_t)(r0 + 8) * F + col) = v;
            }
        }
    }
}

// ---------------- graph segment offsets ----------------
__global__ void k_goff(int b, const void* __restrict__ batch, int N, int slot) {
    int g = threadIdx.x;
    if (g > NG) return;
    int is64 = g_is64[slot];
    int lo = 0, hi = N;
    while (lo < hi) {
        int mid = (lo + hi) >> 1;
        if (idx_at(batch, mid, is64) < g) lo = mid + 1; else hi = mid;
    }
    g_goff[b][g] = lo;
}

// ---------------- global mean pool ----------------
__global__ void k_pool(int b) {
    int g = blockIdx.y;
    int c = blockIdx.x * 128 + threadIdx.x;
    int s = g_goff[b][g], e = g_goff[b][g + 1];
    float sum = 0.0f;
    for (int r = s; r < e; r++) sum += g_y[(size_t)r * F + c];
    float cnt = (float)(e - s);
    g_pool[b][g * F + c] = sum / fmaxf(cnt, 1.0f);
}

// ---------------- fc ----------------
__global__ void k_fc(int b, const float* __restrict__ Wf, const float* __restrict__ bf) {
    __shared__ float p[F];
    int g = blockIdx.x, t = threadIdx.x;
    for (int k = t; k < F; k += 128) p[k] = g_pool[b][g * F + k];
    __syncthreads();
    float acc = 0.0f;
    #pragma unroll 8
    for (int k = 0; k < F; k++) acc += p[k] * Wf[k * DD + t];
    acc += bf[t];
    g_z[b][g * DD + t] = leaky(acc);
}

// ---------------- final ----------------
__global__ void k_final(const float* __restrict__ fW, const float* __restrict__ fb,
                        float* __restrict__ out) {
    __shared__ float sh[256];
    int g = blockIdx.x, t = threadIdx.x;
    float v;
    if (t < DD) v = g_z[0][g * DD + t] * fW[t];
    else        v = g_z[1][g * DD + (t - DD)] * fW[t];
    sh[t] = v;
    __syncthreads();
    #pragma unroll
    for (int s = 128; s > 0; s >>= 1) {
        if (t < s) sh[t] += sh[t + s];
        __syncthreads();
    }
    if (t == 0) out[g] = sh[0] + fb[0];
}

// ---------------- host launcher ----------------
extern "C" void kernel_launch(void* const* d_in, const int* in_sizes, int n_in,
                              void* d_out, int out_size) {
    const float* x1  = (const float*)d_in[0];
    const void*  ei1 = d_in[1];
    const void*  bt1 = d_in[2];
    const float* x2  = (const float*)d_in[3];
    const void*  ei2 = d_in[4];
    const void*  bt2 = d_in[5];
    int wb = n_in - 10;
    const float* c1W = (const float*)d_in[wb + 0];
    const float* c1b = (const float*)d_in[wb + 1];
    const float* f1W = (const float*)d_in[wb + 2];
    const float* f1b = (const float*)d_in[wb + 3];
    const float* c2W = (const float*)d_in[wb + 4];
    const float* c2b = (const float*)d_in[wb + 5];
    const float* f2W = (const float*)d_in[wb + 6];
    const float* f2b = (const float*)d_in[wb + 7];
    const float* fW  = (const float*)d_in[wb + 8];
    const float* fb  = (const float*)d_in[wb + 9];
    float* out = (float*)d_out;

    int N = in_sizes[0] / F;
    int E = in_sizes[1] / 2;

    const float* xs[2]  = {x1, x2};
    const void*  eis[2] = {ei1, ei2};
    const void*  bts[2] = {bt1, bt2};
    const float* cW[2]  = {c1W, c2W};
    const float* cb[2]  = {c1b, c2b};
    const float* fWb[2] = {f1W, f2W};
    const float* fbb[2] = {f1b, f2b};

    cudaFuncSetAttribute(k_tgemm, cudaFuncAttributeMaxDynamicSharedMemorySize, SM_TOT);

    k_detect<<<1, 256>>>((const unsigned int*)ei1, 2 * E, 0);
    k_detect<<<1, 256>>>((const unsigned int*)bt1, N, 1);
    k_detect<<<1, 256>>>((const unsigned int*)ei2, 2 * E, 2);
    k_detect<<<1, 256>>>((const unsigned int*)bt2, N, 3);
    k_zero_deg<<<(2 * MAXN + 255) / 256, 256>>>();

    for (int b = 0; b < 2; b++) {
        int eslot = 2 * b, bslot = 2 * b + 1;

        k_deg<<<(E + 255) / 256, 256>>>(b, eis[b], E, eslot);
        k_dinv<<<(N + 255) / 256, 256>>>(b, N);
        k_scan<<<1, 1024>>>(b, N);
        k_fill<<<(E + 255) / 256, 256>>>(b, eis[b], E, eslot);
        k_agg<<<N, 256>>>(b, xs[b]);

        dim3 wgrid(F / 32, F / 32);
        k_wsplit<<<wgrid, dim3(32, 8)>>>(cW[b]);

        dim3 ggrid(F / 128, (N + 127) / 128);
        k_tgemm<<<ggrid, 256, SM_TOT>>>(cb[b], N);

        k_goff<<<1, NG + 1>>>(b, bts[b], N, bslot);
        dim3 pgrid(F / 128, NG);
        k_pool<<<pgrid, 128>>>(b);
        k_fc<<<NG, DD>>>(b, fWb[b], fbb[b]);
    }

    k_final<<<NG, 256>>>(fW, fb, out);
}

// round 5
// speedup vs baseline: 3.0283x; 1.6098x over previous
#include <cuda_runtime.h>
#include <cuda_fp16.h>
#include <cstdint>
#include <math.h>

#define F    1024
#define MAXN 10000
#define MAXE 80000
#define NG   64
#define DD   128

// ---------------- static device scratch ----------------
__device__ float  g_y[2][(size_t)MAXN * F];      // leaky(agg@W + b)
__device__ __half g_a16[2][(size_t)MAXN * F];    // fp16(agg)
__device__ __half g_wh[2][(size_t)F * F];        // W^T hi fp16  [n][k]
__device__ __half g_wl[2][(size_t)F * F];        // W^T lo fp16  [n][k]
__device__ int   g_deg[2][MAXN];
__device__ float g_dinv[2][MAXN];
__device__ int   g_rowptr[2][MAXN + 1];
__device__ int   g_cursor[2][MAXN];
__device__ int   g_col[2][MAXE];
__device__ int   g_goff[2][NG + 1];
__device__ float g_pool[2][NG * F];
__device__ float g_z[2][NG * DD];
__device__ int   g_is64[4];   // 0: edge b0, 1: batch b0, 2: edge b1, 3: batch b1

__device__ __forceinline__ float leaky(float v) { return v >= 0.0f ? v : 0.01f * v; }

__device__ __forceinline__ int idx_at(const void* p, long long i, int is64) {
    return is64 ? (int)(((const long long*)p)[i]) : ((const int*)p)[i];
}

// ---------------- low-level helpers ----------------
__device__ __forceinline__ uint32_t smem_to_u32(const void* smem_ptr) {
    uint32_t addr;
    asm("{ .reg .u64 tmp; cvta.to.shared.u64 tmp, %1; cvt.u32.u64 %0, tmp; }"
        : "=r"(addr) : "l"(smem_ptr));
    return addr;
}
__device__ __forceinline__ void cp_async16(uint32_t dst, const void* src, bool p) {
    asm volatile("cp.async.cg.shared.global [%0], [%1], 16, %2;"
                 :: "r"(dst), "l"(src), "r"(p ? 16u : 0u) : "memory");
}
__device__ __forceinline__ void cp_commit() {
    asm volatile("cp.async.commit_group;" ::: "memory");
}
template <int N>
__device__ __forceinline__ void cp_wait() {
    asm volatile("cp.async.wait_group %0;" :: "n"(N) : "memory");
}
__device__ __forceinline__ uint32_t lds32(uint32_t addr) {
    uint32_t v;
    asm volatile("ld.shared.b32 %0, [%1];" : "=r"(v) : "r"(addr));
    return v;
}
__device__ __forceinline__ void mma16816(float* c, const uint32_t* a, const uint32_t* b) {
    asm volatile(
        "mma.sync.aligned.m16n8k16.row.col.f32.f16.f16.f32 "
        "{%0,%1,%2,%3}, {%4,%5,%6,%7}, {%8,%9}, {%0,%1,%2,%3};"
        : "+f"(c[0]), "+f"(c[1]), "+f"(c[2]), "+f"(c[3])
        : "r"(a[0]), "r"(a[1]), "r"(a[2]), "r"(a[3]), "r"(b[0]), "r"(b[1]));
}

// ---------------- fused: dtype detect (tail-scan) + deg zeroing ----------------
// blocks 0..3: detect slot; blocks >=4: zero g_deg
__global__ void k_pre(const unsigned int* p0, const unsigned int* p1,
                      const unsigned int* p2, const unsigned int* p3,
                      int nw0, int nw1, int nw2, int nw3) {
    if (blockIdx.x < 4) {
        const unsigned int* p; int nw;
        if (blockIdx.x == 0)      { p = p0; nw = nw0; }
        else if (blockIdx.x == 1) { p = p1; nw = nw1; }
        else if (blockIdx.x == 2) { p = p2; nw = nw2; }
        else                      { p = p3; nw = nw3; }
        int start = nw > 4096 ? nw - 4096 : 0;
        __shared__ unsigned int sh[256];
        unsigned int acc = 0;
        for (int i = start + threadIdx.x; i < nw; i += 256)
            if (i & 1) acc |= p[i];
        sh[threadIdx.x] = acc;
        __syncthreads();
        for (int s = 128; s > 0; s >>= 1) {
            if (threadIdx.x < s) sh[threadIdx.x] |= sh[threadIdx.x + s];
            __syncthreads();
        }
        if (threadIdx.x == 0) g_is64[blockIdx.x] = (sh[0] == 0u) ? 1 : 0;
    } else {
        int i = (blockIdx.x - 4) * 256 + threadIdx.x;
        if (i < 2 * MAXN) ((int*)g_deg)[i] = 0;
    }
}

// ---------------- degree histogram, both branches ----------------
__global__ void k_deg(const void* ei0, const void* ei1, int E) {
    int b = blockIdx.y;
    int e = blockIdx.x * blockDim.x + threadIdx.x;
    if (e < E) {
        const void* ei = b ? ei1 : ei0;
        int is64 = g_is64[2 * b];
        atomicAdd(&g_deg[b][idx_at(ei, (long long)E + e, is64)], 1);
    }
}

// ---------------- per-branch scan (rowptr/cursor) + dinv ----------------
__global__ void k_scan(int N) {
    int b = blockIdx.x;
    __shared__ int sh[1024];
    __shared__ int carry;
    if (threadIdx.x == 0) carry = 0;
    __syncthreads();
    for (int base = 0; base < N; base += 1024) {
        int i = base + threadIdx.x;
        int v = (i < N) ? g_deg[b][i] : 0;
        sh[threadIdx.x] = v;
        __syncthreads();
        #pragma unroll
        for (int off = 1; off < 1024; off <<= 1) {
            int t = (threadIdx.x >= off) ? sh[threadIdx.x - off] : 0;
            __syncthreads();
            sh[threadIdx.x] += t;
            __syncthreads();
        }
        if (i < N) {
            int excl = carry + sh[threadIdx.x] - v;
            g_rowptr[b][i] = excl;
            g_cursor[b][i] = excl;
        }
        __syncthreads();
        if (threadIdx.x == 1023) carry += sh[1023];
        __syncthreads();
    }
    if (threadIdx.x == 0) g_rowptr[b][N] = carry;
    // dinv
    for (int i = threadIdx.x; i < N; i += 1024)
        g_dinv[b][i] = rsqrtf((float)(g_deg[b][i] + 1));
}

// ---------------- CSR fill (both branches) + goff (2 tail blocks) ----------------
__global__ void k_fill(const void* ei0, const void* ei1,
                       const void* bt0, const void* bt1, int E, int N, int nbE) {
    if ((int)blockIdx.x < nbE) {
        int b = blockIdx.y;
        int e = blockIdx.x * blockDim.x + threadIdx.x;
        if (e < E) {
            const void* ei = b ? ei1 : ei0;
            int is64 = g_is64[2 * b];
            int s = idx_at(ei, e, is64);
            int d = idx_at(ei, (long long)E + e, is64);
            int pos = atomicAdd(&g_cursor[b][d], 1);
            g_col[b][pos] = s;
        }
    } else if (blockIdx.y == 0) {
        // goff: blockIdx.x == nbE -> branch 0, nbE+1 -> branch 1
        int b = blockIdx.x - nbE;
        int g = threadIdx.x;
        if (g > NG) return;
        const void* batch = b ? bt1 : bt0;
        int is64 = g_is64[2 * b + 1];
        int lo = 0, hi = N;
        while (lo < hi) {
            int mid = (lo + hi) >> 1;
            if (idx_at(batch, mid, is64) < g) lo = mid + 1; else hi = mid;
        }
        g_goff[b][g] = lo;
    }
}

// ---------------- aggregation (writes fp16 directly), both branches ----------------
__global__ void k_agg(const float* __restrict__ x0, const float* __restrict__ x1) {
    int b = blockIdx.y;
    int row = blockIdx.x;
    int t = threadIdx.x;                       // 256 threads, float4 each
    const float4* __restrict__ x4 = (const float4*)(b ? x1 : x0);
    float dv = g_dinv[b][row];
    float4 xr = __ldg(&x4[(size_t)row * 256 + t]);
    float w0 = dv * dv;
    float4 acc;
    acc.x = xr.x * w0; acc.y = xr.y * w0; acc.z = xr.z * w0; acc.w = xr.w * w0;
    int s = g_rowptr[b][row], e = g_rowptr[b][row + 1];
    for (int j = s; j < e; j++) {
        int u = g_col[b][j];
        float w = g_dinv[b][u] * dv;
        float4 xu = __ldg(&x4[(size_t)u * 256 + t]);
        acc.x += xu.x * w; acc.y += xu.y * w; acc.z += xu.z * w; acc.w += xu.w * w;
    }
    __half2 p0 = __floats2half2_rn(acc.x, acc.y);
    __half2 p1 = __floats2half2_rn(acc.z, acc.w);
    uint2 v;
    v.x = *(uint32_t*)&p0; v.y = *(uint32_t*)&p1;
    ((uint2*)g_a16[b])[(size_t)row * 256 + t] = v;
}

// ---------------- W transpose + fp16 hi/lo split, both branches ----------------
__global__ void k_wsplit(const float* __restrict__ W0, const float* __restrict__ W1) {
    int b = blockIdx.z;
    const float* __restrict__ W = b ? W1 : W0;
    __shared__ float t[32][33];
    int tx = threadIdx.x, ty = threadIdx.y;
    int x = blockIdx.x * 32 + tx;
    #pragma unroll
    for (int j = 0; j < 4; j++) {
        int y = blockIdx.y * 32 + ty + j * 8;
        t[ty + j * 8][tx] = W[(size_t)y * F + x];
    }
    __syncthreads();
    int xo = blockIdx.y * 32 + tx;  // k
    #pragma unroll
    for (int j = 0; j < 4; j++) {
        int yo = blockIdx.x * 32 + ty + j * 8;  // n
        float v = t[tx][ty + j * 8];
        __half h = __float2half_rn(v);
        __half l = __float2half_rn(v - __half2float(h));
        g_wh[b][(size_t)yo * F + xo] = h;
        g_wl[b][(size_t)yo * F + xo] = l;
    }
}

// ---------------- split-fp16 HMMA GEMM: Y = leaky(A@(Whi+Wlo) + bias) ----------------
// CTA tile 128x128, K chunk 32, 2-stage cp.async double buffer, both branches (z).
// 8 warps: warp_m = wid&1 (64 rows), warp_n = wid>>1 (32 cols).
#define BK        32
#define NCHUNK    (F / BK)           // 32
#define ROWPAD    40                  // fp16 elems per smem row (32 data + 8 pad)
#define SA_BYTES  (128 * ROWPAD * 2)  // 10240 per tensor
#define STG_BYTES (3 * SA_BYTES)      // A, Whi, Wlo
#define SM_TOT    (2 * STG_BYTES)     // 61440

__global__ __launch_bounds__(256)
void k_tgemm(const float* __restrict__ bias0, const float* __restrict__ bias1, int M) {
    extern __shared__ char smem[];
    uint32_t sb = smem_to_u32(smem);
    int br = blockIdx.z;
    const float* __restrict__ bias = br ? bias1 : bias0;
    const __half* __restrict__ A  = g_a16[br];
    const __half* __restrict__ Wh = g_wh[br];
    const __half* __restrict__ Wl = g_wl[br];

    int tid = threadIdx.x;
    int wid = tid >> 5, lane = tid & 31;
    int gid = lane >> 2, tig = lane & 3;
    int warp_m = wid & 1, warp_n = wid >> 1;
    int m0 = blockIdx.y * 128;
    int n0 = blockIdx.x * 128;

    float acc[4][4][4];
    #pragma unroll
    for (int i = 0; i < 4; i++)
        #pragma unroll
        for (int j = 0; j < 4; j++)
            #pragma unroll
            for (int q = 0; q < 4; q++) acc[i][j][q] = 0.0f;

    auto load_chunk = [&](int c, int s) {
        uint32_t stg = sb + s * STG_BYTES;
        int k0 = c * BK;
        #pragma unroll
        for (int l = 0; l < 6; l++) {
            int idx = l * 256 + tid;
            int tsr = idx >> 9;        // 0 A, 1 Whi, 2 Wlo
            int rem = idx & 511;
            int row = rem >> 2;
            int c16 = rem & 3;
            const __half* gsrc;
            bool pred = true;
            if (tsr == 0) {
                int grow = m0 + row;
                pred = grow < M;
                gsrc = A + (size_t)(pred ? grow : 0) * F + k0 + c16 * 8;
            } else {
                const __half* base = (tsr == 1) ? Wh : Wl;
                gsrc = base + (size_t)(n0 + row) * F + k0 + c16 * 8;
            }
            uint32_t sdst = stg + tsr * SA_BYTES + row * (ROWPAD * 2) + c16 * 16;
            cp_async16(sdst, gsrc, pred);
        }
        cp_commit();
    };

    load_chunk(0, 0);

    for (int c = 0; c < NCHUNK; c++) {
        int s = c & 1;
        if (c + 1 < NCHUNK) {
            load_chunk(c + 1, s ^ 1);
            cp_wait<1>();
        } else {
            cp_wait<0>();
        }
        __syncthreads();

        uint32_t sa  = sb + s * STG_BYTES;
        uint32_t sbh = sa + SA_BYTES;
        uint32_t sbl = sa + 2 * SA_BYTES;

        #pragma unroll
        for (int ks = 0; ks < 2; ks++) {
            int kb = ks * 16;
            uint32_t bh[4][2], bl[4][2];
            #pragma unroll
            for (int nt = 0; nt < 4; nt++) {
                int n = warp_n * 32 + nt * 8 + gid;
                uint32_t o = n * (ROWPAD * 2) + (kb + tig * 2) * 2;
                bh[nt][0] = lds32(sbh + o);
                bh[nt][1] = lds32(sbh + o + 16);
                bl[nt][0] = lds32(sbl + o);
                bl[nt][1] = lds32(sbl + o + 16);
            }
            #pragma unroll
            for (int mt = 0; mt < 4; mt++) {
                int r = warp_m * 64 + mt * 16 + gid;
                uint32_t o = r * (ROWPAD * 2) + (kb + tig * 2) * 2;
                uint32_t ah[4];
                ah[0] = lds32(sa + o);
                ah[1] = lds32(sa + o + 8 * (ROWPAD * 2));
                ah[2] = lds32(sa + o + 16);
                ah[3] = lds32(sa + o + 8 * (ROWPAD * 2) + 16);
                #pragma unroll
                for (int nt = 0; nt < 4; nt++) {
                    mma16816(acc[mt][nt], ah, bh[nt]);
                    mma16816(acc[mt][nt], ah, bl[nt]);
                }
            }
        }
        __syncthreads();
    }

    // ---- epilogue: bias + leaky, store fp32 ----
    float* __restrict__ Y = g_y[br];
    #pragma unroll
    for (int mt = 0; mt < 4; mt++) {
        int r0 = m0 + warp_m * 64 + mt * 16 + gid;
        #pragma unroll
        for (int nt = 0; nt < 4; nt++) {
            int col = n0 + warp_n * 32 + nt * 8 + tig * 2;
            float b0 = __ldg(&bias[col]);
            float b1 = __ldg(&bias[col + 1]);
            float* cf = acc[mt][nt];
            if (r0 < M) {
                float2 v = {leaky(cf[0] + b0), leaky(cf[1] + b1)};
                *(float2*)(Y + (size_t)r0 * F + col) = v;
            }
            if (r0 + 8 < M) {
                float2 v = {leaky(cf[2] + b0), leaky(cf[3] + b1)};
                *(float2*)(Y + (size_t)(r0 + 8) * F + col) = v;
            }
        }
    }
}

// ---------------- global mean pool, both branches ----------------
__global__ void k_pool() {
    int b = blockIdx.z;
    int g = blockIdx.y;
    int c = blockIdx.x * 128 + threadIdx.x;
    int s = g_goff[b][g], e = g_goff[b][g + 1];
    float sum = 0.0f;
    for (int r = s; r < e; r++) sum += g_y[b][(size_t)r * F + c];
    float cnt = (float)(e - s);
    g_pool[b][g * F + c] = sum / fmaxf(cnt, 1.0f);
}

// ---------------- fc, both branches ----------------
__global__ void k_fc(const float* __restrict__ Wf0, const float* __restrict__ bf0,
                     const float* __restrict__ Wf1, const float* __restrict__ bf1) {
    int b = blockIdx.y;
    const float* __restrict__ Wf = b ? Wf1 : Wf0;
    const float* __restrict__ bf = b ? bf1 : bf0;
    __shared__ float p[F];
    int g = blockIdx.x, t = threadIdx.x;
    for (int k = t; k < F; k += 128) p[k] = g_pool[b][g * F + k];
    __syncthreads();
    float acc = 0.0f;
    #pragma unroll 8
    for (int k = 0; k < F; k++) acc += p[k] * Wf[k * DD + t];
    acc += bf[t];
    g_z[b][g * DD + t] = leaky(acc);
}

// ---------------- final ----------------
__global__ void k_final(const float* __restrict__ fW, const float* __restrict__ fb,
                        float* __restrict__ out) {
    __shared__ float sh[256];
    int g = blockIdx.x, t = threadIdx.x;
    float v;
    if (t < DD) v = g_z[0][g * DD + t] * fW[t];
    else        v = g_z[1][g * DD + (t - DD)] * fW[t];
    sh[t] = v;
    __syncthreads();
    #pragma unroll
    for (int s = 128; s > 0; s >>= 1) {
        if (t < s) sh[t] += sh[t + s];
        __syncthreads();
    }
    if (t == 0) out[g] = sh[0] + fb[0];
}

// ---------------- host launcher ----------------
extern "C" void kernel_launch(void* const* d_in, const int* in_sizes, int n_in,
                              void* d_out, int out_size) {
    const float* x1  = (const float*)d_in[0];
    const void*  ei1 = d_in[1];
    const void*  bt1 = d_in[2];
    const float* x2  = (const float*)d_in[3];
    const void*  ei2 = d_in[4];
    const void*  bt2 = d_in[5];
    int wb = n_in - 10;
    const float* c1W = (const float*)d_in[wb + 0];
    const float* c1b = (const float*)d_in[wb + 1];
    const float* f1W = (const float*)d_in[wb + 2];
    const float* f1b = (const float*)d_in[wb + 3];
    const float* c2W = (const float*)d_in[wb + 4];
    const float* c2b = (const float*)d_in[wb + 5];
    const float* f2W = (const float*)d_in[wb + 6];
    const float* f2b = (const float*)d_in[wb + 7];
    const float* fW  = (const float*)d_in[wb + 8];
    const float* fb  = (const float*)d_in[wb + 9];
    float* out = (float*)d_out;

    int N = in_sizes[0] / F;
    int E = in_sizes[1] / 2;

    cudaFuncSetAttribute(k_tgemm, cudaFuncAttributeMaxDynamicSharedMemorySize, SM_TOT);

    // 1. detect (4 blocks) + zero deg
    int zb = (2 * MAXN + 255) / 256;
    k_pre<<<4 + zb, 256>>>((const unsigned int*)ei1, (const unsigned int*)bt1,
                           (const unsigned int*)ei2, (const unsigned int*)bt2,
                           2 * E, N, 2 * E, N);
    // 2. degree histogram
    int nbE = (E + 255) / 256;
    k_deg<<<dim3(nbE, 2), 256>>>(ei1, ei2, E);
    // 3. scan + dinv (one block per branch)
    k_scan<<<2, 1024>>>(N);
    // 4. CSR fill + goff
    k_fill<<<dim3(nbE + 2, 2), 256>>>(ei1, ei2, bt1, bt2, E, N, nbE);
    // 5. aggregation (fp16 out)
    k_agg<<<dim3(N, 2), 256>>>(x1, x2);
    // 6. weight transpose + split
    k_wsplit<<<dim3(F / 32, F / 32, 2), dim3(32, 8)>>>(c1W, c2W);
    // 7. GEMM (both branches)
    k_tgemm<<<dim3(F / 128, (N + 127) / 128, 2), 256, SM_TOT>>>(c1b, c2b, N);
    // 8. pool
    k_pool<<<dim3(F / 128, NG, 2), 128>>>();
    // 9. fc
    k_fc<<<dim3(NG, 2), DD>>>(f1W, f1b, f2W, f2b);
    // 10. final
    k_final<<<NG, 256>>>(fW, fb, out);
}

// round 6
// speedup vs baseline: 4.0845x; 1.3488x over previous
#include <cuda_runtime.h>
#include <cuda_fp16.h>
#include <cstdint>
#include <math.h>

#define F    1024
#define MAXN 10000
#define MAXE 80000
#define NG   64
#define DD   128

// ---------------- static device scratch ----------------
__device__ float  g_y[2][(size_t)MAXN * F];      // leaky(agg@W + b)  fp32 (accuracy)
__device__ __half g_a16[2][(size_t)MAXN * F];    // fp16(agg)
__device__ __half g_wh[2][(size_t)F * F];        // fp16(W^T)  [n][k]
__device__ int   g_deg[2][MAXN];
__device__ float g_dinv[2][MAXN];
__device__ int   g_rowptr[2][MAXN + 1];
__device__ int   g_cursor[2][MAXN];
__device__ int   g_col[2][MAXE];
__device__ int   g_goff[2][NG + 1];
__device__ float g_pool[2][NG * F];
__device__ float g_z[2][NG * DD];
__device__ int   g_is64[4];   // 0: edge b0, 1: batch b0, 2: edge b1, 3: batch b1

__device__ __forceinline__ float leaky(float v) { return v >= 0.0f ? v : 0.01f * v; }

__device__ __forceinline__ int idx_at(const void* p, long long i, int is64) {
    return is64 ? (int)(((const long long*)p)[i]) : ((const int*)p)[i];
}

// ---------------- low-level helpers ----------------
__device__ __forceinline__ uint32_t smem_to_u32(const void* smem_ptr) {
    uint32_t addr;
    asm("{ .reg .u64 tmp; cvta.to.shared.u64 tmp, %1; cvt.u32.u64 %0, tmp; }"
        : "=r"(addr) : "l"(smem_ptr));
    return addr;
}
__device__ __forceinline__ void cp_async16(uint32_t dst, const void* src, bool p) {
    asm volatile("cp.async.cg.shared.global [%0], [%1], 16, %2;"
                 :: "r"(dst), "l"(src), "r"(p ? 16u : 0u) : "memory");
}
__device__ __forceinline__ void cp_commit() {
    asm volatile("cp.async.commit_group;" ::: "memory");
}
template <int N>
__device__ __forceinline__ void cp_wait() {
    asm volatile("cp.async.wait_group %0;" :: "n"(N) : "memory");
}
__device__ __forceinline__ uint32_t lds32(uint32_t addr) {
    uint32_t v;
    asm volatile("ld.shared.b32 %0, [%1];" : "=r"(v) : "r"(addr));
    return v;
}
__device__ __forceinline__ void mma16816(float* c, const uint32_t* a, const uint32_t* b) {
    asm volatile(
        "mma.sync.aligned.m16n8k16.row.col.f32.f16.f16.f32 "
        "{%0,%1,%2,%3}, {%4,%5,%6,%7}, {%8,%9}, {%0,%1,%2,%3};"
        : "+f"(c[0]), "+f"(c[1]), "+f"(c[2]), "+f"(c[3])
        : "r"(a[0]), "r"(a[1]), "r"(a[2]), "r"(a[3]), "r"(b[0]), "r"(b[1]));
}

// ---------------- fused: dtype detect (tail-scan) + deg zeroing ----------------
__global__ void k_pre(const unsigned int* p0, const unsigned int* p1,
                      const unsigned int* p2, const unsigned int* p3,
                      int nw0, int nw1, int nw2, int nw3) {
    if (blockIdx.x < 4) {
        const unsigned int* p; int nw;
        if (blockIdx.x == 0)      { p = p0; nw = nw0; }
        else if (blockIdx.x == 1) { p = p1; nw = nw1; }
        else if (blockIdx.x == 2) { p = p2; nw = nw2; }
        else                      { p = p3; nw = nw3; }
        int start = nw > 4096 ? nw - 4096 : 0;
        __shared__ unsigned int sh[256];
        unsigned int acc = 0;
        for (int i = start + threadIdx.x; i < nw; i += 256)
            if (i & 1) acc |= p[i];
        sh[threadIdx.x] = acc;
        __syncthreads();
        for (int s = 128; s > 0; s >>= 1) {
            if (threadIdx.x < s) sh[threadIdx.x] |= sh[threadIdx.x + s];
            __syncthreads();
        }
        if (threadIdx.x == 0) g_is64[blockIdx.x] = (sh[0] == 0u) ? 1 : 0;
    } else {
        int i = (blockIdx.x - 4) * 256 + threadIdx.x;
        if (i < 2 * MAXN) ((int*)g_deg)[i] = 0;
    }
}

// ---------------- degree histogram, both branches ----------------
__global__ void k_deg(const void* ei0, const void* ei1, int E) {
    int b = blockIdx.y;
    int e = blockIdx.x * blockDim.x + threadIdx.x;
    if (e < E) {
        const void* ei = b ? ei1 : ei0;
        int is64 = g_is64[2 * b];
        atomicAdd(&g_deg[b][idx_at(ei, (long long)E + e, is64)], 1);
    }
}

// ---------------- per-branch scan (rowptr/cursor) + dinv ----------------
__global__ void k_scan(int N) {
    int b = blockIdx.x;
    __shared__ int sh[1024];
    __shared__ int carry;
    if (threadIdx.x == 0) carry = 0;
    __syncthreads();
    for (int base = 0; base < N; base += 1024) {
        int i = base + threadIdx.x;
        int v = (i < N) ? g_deg[b][i] : 0;
        sh[threadIdx.x] = v;
        __syncthreads();
        #pragma unroll
        for (int off = 1; off < 1024; off <<= 1) {
            int t = (threadIdx.x >= off) ? sh[threadIdx.x - off] : 0;
            __syncthreads();
            sh[threadIdx.x] += t;
            __syncthreads();
        }
        if (i < N) {
            int excl = carry + sh[threadIdx.x] - v;
            g_rowptr[b][i] = excl;
            g_cursor[b][i] = excl;
        }
        __syncthreads();
        if (threadIdx.x == 1023) carry += sh[1023];
        __syncthreads();
    }
    if (threadIdx.x == 0) g_rowptr[b][N] = carry;
    for (int i = threadIdx.x; i < N; i += 1024)
        g_dinv[b][i] = rsqrtf((float)(g_deg[b][i] + 1));
}

// ---------------- CSR fill (both branches) + goff (2 tail blocks) ----------------
__global__ void k_fill(const void* ei0, const void* ei1,
                       const void* bt0, const void* bt1, int E, int N, int nbE) {
    if ((int)blockIdx.x < nbE) {
        int b = blockIdx.y;
        int e = blockIdx.x * blockDim.x + threadIdx.x;
        if (e < E) {
            const void* ei = b ? ei1 : ei0;
            int is64 = g_is64[2 * b];
            int s = idx_at(ei, e, is64);
            int d = idx_at(ei, (long long)E + e, is64);
            int pos = atomicAdd(&g_cursor[b][d], 1);
            g_col[b][pos] = s;
        }
    } else if (blockIdx.y == 0) {
        int b = blockIdx.x - nbE;
        int g = threadIdx.x;
        if (g > NG) return;
        const void* batch = b ? bt1 : bt0;
        int is64 = g_is64[2 * b + 1];
        int lo = 0, hi = N;
        while (lo < hi) {
            int mid = (lo + hi) >> 1;
            if (idx_at(batch, mid, is64) < g) lo = mid + 1; else hi = mid;
        }
        g_goff[b][g] = lo;
    }
}

// ---------------- aggregation (writes fp16 directly), both branches ----------------
__global__ void k_agg(const float* __restrict__ x0, const float* __restrict__ x1) {
    int b = blockIdx.y;
    int row = blockIdx.x;
    int t = threadIdx.x;                       // 256 threads, float4 each
    const float4* __restrict__ x4 = (const float4*)(b ? x1 : x0);
    float dv = g_dinv[b][row];
    float4 xr = __ldg(&x4[(size_t)row * 256 + t]);
    float w0 = dv * dv;
    float4 acc;
    acc.x = xr.x * w0; acc.y = xr.y * w0; acc.z = xr.z * w0; acc.w = xr.w * w0;
    int s = g_rowptr[b][row], e = g_rowptr[b][row + 1];
    for (int j = s; j < e; j++) {
        int u = g_col[b][j];
        float w = g_dinv[b][u] * dv;
        float4 xu = __ldg(&x4[(size_t)u * 256 + t]);
        acc.x += xu.x * w; acc.y += xu.y * w; acc.z += xu.z * w; acc.w += xu.w * w;
    }
    __half2 p0 = __floats2half2_rn(acc.x, acc.y);
    __half2 p1 = __floats2half2_rn(acc.z, acc.w);
    uint2 v;
    v.x = *(uint32_t*)&p0; v.y = *(uint32_t*)&p1;
    ((uint2*)g_a16[b])[(size_t)row * 256 + t] = v;
}

// ---------------- W transpose + fp16 convert, both branches ----------------
__global__ void k_wt(const float* __restrict__ W0, const float* __restrict__ W1) {
    int b = blockIdx.z;
    const float* __restrict__ W = b ? W1 : W0;
    __shared__ float t[32][33];
    int tx = threadIdx.x, ty = threadIdx.y;
    int x = blockIdx.x * 32 + tx;
    #pragma unroll
    for (int j = 0; j < 4; j++) {
        int y = blockIdx.y * 32 + ty + j * 8;
        t[ty + j * 8][tx] = W[(size_t)y * F + x];
    }
    __syncthreads();
    int xo = blockIdx.y * 32 + tx;  // k
    #pragma unroll
    for (int j = 0; j < 4; j++) {
        int yo = blockIdx.x * 32 + ty + j * 8;  // n
        g_wh[b][(size_t)yo * F + xo] = __float2half_rn(t[tx][ty + j * 8]);
    }
}

// ---------------- fp16 HMMA GEMM: Y = leaky(A@W + bias) ----------------
// CTA tile 128x128, K chunk 64, 2-stage cp.async double buffer, both branches (z).
// 8 warps: warp_m = wid&1 (64 rows), warp_n = wid>>1 (32 cols).
#define BK        64
#define NCHUNK    (F / BK)            // 16
#define ROWPAD    72                   // fp16 elems per smem row (64 data + 8 pad)
#define SA_BYTES  (128 * ROWPAD * 2)   // 18432 per tensor
#define STG_BYTES (2 * SA_BYTES)       // A, W
#define SM_TOT    (2 * STG_BYTES)      // 73728

__global__ __launch_bounds__(256)
void k_tgemm(const float* __restrict__ bias0, const float* __restrict__ bias1, int M) {
    extern __shared__ char smem[];
    uint32_t sb = smem_to_u32(smem);
    int br = blockIdx.z;
    const float* __restrict__ bias = br ? bias1 : bias0;
    const __half* __restrict__ A  = g_a16[br];
    const __half* __restrict__ Wh = g_wh[br];

    int tid = threadIdx.x;
    int wid = tid >> 5, lane = tid & 31;
    int gid = lane >> 2, tig = lane & 3;
    int warp_m = wid & 1, warp_n = wid >> 1;
    int m0 = blockIdx.y * 128;
    int n0 = blockIdx.x * 128;

    float acc[4][4][4];
    #pragma unroll
    for (int i = 0; i < 4; i++)
        #pragma unroll
        for (int j = 0; j < 4; j++)
            #pragma unroll
            for (int q = 0; q < 4; q++) acc[i][j][q] = 0.0f;

    auto load_chunk = [&](int c, int s) {
        uint32_t stg = sb + s * STG_BYTES;
        int k0 = c * BK;
        #pragma unroll
        for (int l = 0; l < 8; l++) {
            int idx = l * 256 + tid;     // 0..2047
            int tsr = idx >> 10;          // 0 A, 1 W
            int rem = idx & 1023;
            int row = rem >> 3;           // 0..127
            int c16 = rem & 7;            // 8 x 16B = 128B = 64 fp16
            const __half* gsrc;
            bool pred = true;
            if (tsr == 0) {
                int grow = m0 + row;
                pred = grow < M;
                gsrc = A + (size_t)(pred ? grow : 0) * F + k0 + c16 * 8;
            } else {
                gsrc = Wh + (size_t)(n0 + row) * F + k0 + c16 * 8;
            }
            uint32_t sdst = stg + tsr * SA_BYTES + row * (ROWPAD * 2) + c16 * 16;
            cp_async16(sdst, gsrc, pred);
        }
        cp_commit();
    };

    load_chunk(0, 0);

    for (int c = 0; c < NCHUNK; c++) {
        int s = c & 1;
        if (c + 1 < NCHUNK) {
            load_chunk(c + 1, s ^ 1);
            cp_wait<1>();
        } else {
            cp_wait<0>();
        }
        __syncthreads();

        uint32_t sa  = sb + s * STG_BYTES;
        uint32_t sbh = sa + SA_BYTES;

        #pragma unroll
        for (int ks = 0; ks < 4; ks++) {
            int kb = ks * 16;
            uint32_t bh[4][2];
            #pragma unroll
            for (int nt = 0; nt < 4; nt++) {
                int n = warp_n * 32 + nt * 8 + gid;
                uint32_t o = n * (ROWPAD * 2) + (kb + tig * 2) * 2;
                bh[nt][0] = lds32(sbh + o);
                bh[nt][1] = lds32(sbh + o + 16);
            }
            #pragma unroll
            for (int mt = 0; mt < 4; mt++) {
                int r = warp_m * 64 + mt * 16 + gid;
                uint32_t o = r * (ROWPAD * 2) + (kb + tig * 2) * 2;
                uint32_t ah[4];
                ah[0] = lds32(sa + o);
                ah[1] = lds32(sa + o + 8 * (ROWPAD * 2));
                ah[2] = lds32(sa + o + 16);
                ah[3] = lds32(sa + o + 8 * (ROWPAD * 2) + 16);
                #pragma unroll
                for (int nt = 0; nt < 4; nt++) {
                    mma16816(acc[mt][nt], ah, bh[nt]);
                }
            }
        }
        __syncthreads();
    }

    // ---- epilogue: bias + leaky, store fp32 ----
    float* __restrict__ Y = g_y[br];
    #pragma unroll
    for (int mt = 0; mt < 4; mt++) {
        int r0 = m0 + warp_m * 64 + mt * 16 + gid;
        #pragma unroll
        for (int nt = 0; nt < 4; nt++) {
            int col = n0 + warp_n * 32 + nt * 8 + tig * 2;
            float b0 = __ldg(&bias[col]);
            float b1 = __ldg(&bias[col + 1]);
            float* cf = acc[mt][nt];
            if (r0 < M) {
                float2 v = {leaky(cf[0] + b0), leaky(cf[1] + b1)};
                *(float2*)(Y + (size_t)r0 * F + col) = v;
            }
            if (r0 + 8 < M) {
                float2 v = {leaky(cf[2] + b0), leaky(cf[3] + b1)};
                *(float2*)(Y + (size_t)(r0 + 8) * F + col) = v;
            }
        }
    }
}

// ---------------- global mean pool, both branches ----------------
__global__ void k_pool() {
    int b = blockIdx.z;
    int g = blockIdx.y;
    int c = blockIdx.x * 128 + threadIdx.x;
    int s = g_goff[b][g], e = g_goff[b][g + 1];
    float sum = 0.0f;
    for (int r = s; r < e; r++) sum += g_y[b][(size_t)r * F + c];
    float cnt = (float)(e - s);
    g_pool[b][g * F + c] = sum / fmaxf(cnt, 1.0f);
}

// ---------------- fc, both branches ----------------
__global__ void k_fc(const float* __restrict__ Wf0, const float* __restrict__ bf0,
                     const float* __restrict__ Wf1, const float* __restrict__ bf1) {
    int b = blockIdx.y;
    const float* __restrict__ Wf = b ? Wf1 : Wf0;
    const float* __restrict__ bf = b ? bf1 : bf0;
    __shared__ float p[F];
    int g = blockIdx.x, t = threadIdx.x;
    for (int k = t; k < F; k += 128) p[k] = g_pool[b][g * F + k];
    __syncthreads();
    float acc = 0.0f;
    #pragma unroll 8
    for (int k = 0; k < F; k++) acc += p[k] * Wf[k * DD + t];
    acc += bf[t];
    g_z[b][g * DD + t] = leaky(acc);
}

// ---------------- final ----------------
__global__ void k_final(const float* __restrict__ fW, const float* __restrict__ fb,
                        float* __restrict__ out) {
    __shared__ float sh[256];
    int g = blockIdx.x, t = threadIdx.x;
    float v;
    if (t < DD) v = g_z[0][g * DD + t] * fW[t];
    else        v = g_z[1][g * DD + (t - DD)] * fW[t];
    sh[t] = v;
    __syncthreads();
    #pragma unroll
    for (int s = 128; s > 0; s >>= 1) {
        if (t < s) sh[t] += sh[t + s];
        __syncthreads();
    }
    if (t == 0) out[g] = sh[0] + fb[0];
}

// ---------------- host launcher ----------------
extern "C" void kernel_launch(void* const* d_in, const int* in_sizes, int n_in,
                              void* d_out, int out_size) {
    const float* x1  = (const float*)d_in[0];
    const void*  ei1 = d_in[1];
    const void*  bt1 = d_in[2];
    const float* x2  = (const float*)d_in[3];
    const void*  ei2 = d_in[4];
    const void*  bt2 = d_in[5];
    int wb = n_in - 10;
    const float* c1W = (const float*)d_in[wb + 0];
    const float* c1b = (const float*)d_in[wb + 1];
    const float* f1W = (const float*)d_in[wb + 2];
    const float* f1b = (const float*)d_in[wb + 3];
    const float* c2W = (const float*)d_in[wb + 4];
    const float* c2b = (const float*)d_in[wb + 5];
    const float* f2W = (const float*)d_in[wb + 6];
    const float* f2b = (const float*)d_in[wb + 7];
    const float* fW  = (const float*)d_in[wb + 8];
    const float* fb  = (const float*)d_in[wb + 9];
    float* out = (float*)d_out;

    int N = in_sizes[0] / F;
    int E = in_sizes[1] / 2;

    cudaFuncSetAttribute(k_tgemm, cudaFuncAttributeMaxDynamicSharedMemorySize, SM_TOT);

    int zb = (2 * MAXN + 255) / 256;
    k_pre<<<4 + zb, 256>>>((const unsigned int*)ei1, (const unsigned int*)bt1,
                           (const unsigned int*)ei2, (const unsigned int*)bt2,
                           2 * E, N, 2 * E, N);
    int nbE = (E + 255) / 256;
    k_deg<<<dim3(nbE, 2), 256>>>(ei1, ei2, E);
    k_scan<<<2, 1024>>>(N);
    k_fill<<<dim3(nbE + 2, 2), 256>>>(ei1, ei2, bt1, bt2, E, N, nbE);
    k_agg<<<dim3(N, 2), 256>>>(x1, x2);
    k_wt<<<dim3(F / 32, F / 32, 2), dim3(32, 8)>>>(c1W, c2W);
    k_tgemm<<<dim3(F / 128, (N + 127) / 128, 2), 256, SM_TOT>>>(c1b, c2b, N);
    k_pool<<<dim3(F / 128, NG, 2), 128>>>();
    k_fc<<<dim3(NG, 2), DD>>>(f1W, f1b, f2W, f2b);
    k_final<<<NG, 256>>>(fW, fb, out);
}

// round 7
// speedup vs baseline: 4.1366x; 1.0128x over previous
#include <cuda_runtime.h>
#include <cuda_fp16.h>
#include <cstdint>
#include <math.h>

#define F    1024
#define MAXN 10000
#define MAXE 80000
#define NG   64
#define DD   128

// ---------------- static device scratch ----------------
__device__ __half g_x16[2][(size_t)MAXN * F];    // fp16(x)
__device__ __half g_y16[2][(size_t)MAXN * F];    // fp16(leaky(agg@W + b))
__device__ __half g_a16[2][(size_t)MAXN * F];    // fp16(agg)
__device__ __half g_wh[2][(size_t)F * F];        // fp16(W^T)  [n][k]
__device__ int   g_deg[2][MAXN];
__device__ float g_dinv[2][MAXN];
__device__ int   g_rowptr[2][MAXN + 1];
__device__ int   g_cursor[2][MAXN];
__device__ int   g_col[2][MAXE];
__device__ int   g_goff[2][NG + 1];
__device__ float g_pool[2][NG * F];
__device__ float g_z[2][NG * DD];
__device__ int   g_is64[4];   // 0: edge b0, 1: batch b0, 2: edge b1, 3: batch b1

__device__ __forceinline__ float leaky(float v) { return v >= 0.0f ? v : 0.01f * v; }

__device__ __forceinline__ int idx_at(const void* p, long long i, int is64) {
    return is64 ? (int)(((const long long*)p)[i]) : ((const int*)p)[i];
}

// ---------------- low-level helpers ----------------
__device__ __forceinline__ uint32_t smem_to_u32(const void* smem_ptr) {
    uint32_t addr;
    asm("{ .reg .u64 tmp; cvta.to.shared.u64 tmp, %1; cvt.u32.u64 %0, tmp; }"
        : "=r"(addr) : "l"(smem_ptr));
    return addr;
}
__device__ __forceinline__ void cp_async16(uint32_t dst, const void* src, bool p) {
    asm volatile("cp.async.cg.shared.global [%0], [%1], 16, %2;"
                 :: "r"(dst), "l"(src), "r"(p ? 16u : 0u) : "memory");
}
__device__ __forceinline__ void cp_commit() {
    asm volatile("cp.async.commit_group;" ::: "memory");
}
template <int N>
__device__ __forceinline__ void cp_wait() {
    asm volatile("cp.async.wait_group %0;" :: "n"(N) : "memory");
}
__device__ __forceinline__ uint32_t lds32(uint32_t addr) {
    uint32_t v;
    asm volatile("ld.shared.b32 %0, [%1];" : "=r"(v) : "r"(addr));
    return v;
}
__device__ __forceinline__ void mma16816(float* c, const uint32_t* a, const uint32_t* b) {
    asm volatile(
        "mma.sync.aligned.m16n8k16.row.col.f32.f16.f16.f32 "
        "{%0,%1,%2,%3}, {%4,%5,%6,%7}, {%8,%9}, {%0,%1,%2,%3};"
        : "+f"(c[0]), "+f"(c[1]), "+f"(c[2]), "+f"(c[3])
        : "r"(a[0]), "r"(a[1]), "r"(a[2]), "r"(a[3]), "r"(b[0]), "r"(b[1]));
}

// ---------------- fused: dtype detect + deg zeroing + x->fp16 convert ----------------
// blocks [0,4): detect; [4, 4+zb): zero deg; [4+zb, ...): convert x (both branches)
__global__ void k_pre(const unsigned int* p0, const unsigned int* p1,
                      const unsigned int* p2, const unsigned int* p3,
                      int nw0, int nw1, int nw2, int nw3,
                      const float* __restrict__ x0, const float* __restrict__ x1,
                      int zb, int total4) {
    if (blockIdx.x < 4) {
        const unsigned int* p; int nw;
        if (blockIdx.x == 0)      { p = p0; nw = nw0; }
        else if (blockIdx.x == 1) { p = p1; nw = nw1; }
        else if (blockIdx.x == 2) { p = p2; nw = nw2; }
        else                      { p = p3; nw = nw3; }
        int start = nw > 4096 ? nw - 4096 : 0;
        __shared__ unsigned int sh[256];
        unsigned int acc = 0;
        for (int i = start + threadIdx.x; i < nw; i += 256)
            if (i & 1) acc |= p[i];
        sh[threadIdx.x] = acc;
        __syncthreads();
        for (int s = 128; s > 0; s >>= 1) {
            if (threadIdx.x < s) sh[threadIdx.x] |= sh[threadIdx.x + s];
            __syncthreads();
        }
        if (threadIdx.x == 0) g_is64[blockIdx.x] = (sh[0] == 0u) ? 1 : 0;
    } else if ((int)blockIdx.x < 4 + zb) {
        int i = (blockIdx.x - 4) * 256 + threadIdx.x;
        if (i < 2 * MAXN) ((int*)g_deg)[i] = 0;
    } else {
        // convert x -> fp16, 4 elements per thread
        long long i = (long long)(blockIdx.x - 4 - zb) * 256 + threadIdx.x;
        int b = (i >= total4);
        long long li = b ? i - total4 : i;
        if (li < total4) {
            const float4* __restrict__ x4 = (const float4*)(b ? x1 : x0);
            float4 v = __ldg(&x4[li]);
            __half2 h0 = __floats2half2_rn(v.x, v.y);
            __half2 h1 = __floats2half2_rn(v.z, v.w);
            uint2 u;
            u.x = *(uint32_t*)&h0; u.y = *(uint32_t*)&h1;
            ((uint2*)g_x16[b])[li] = u;
        }
    }
}

// ---------------- degree histogram, both branches ----------------
__global__ void k_deg(const void* ei0, const void* ei1, int E) {
    int b = blockIdx.y;
    int e = blockIdx.x * blockDim.x + threadIdx.x;
    if (e < E) {
        const void* ei = b ? ei1 : ei0;
        int is64 = g_is64[2 * b];
        atomicAdd(&g_deg[b][idx_at(ei, (long long)E + e, is64)], 1);
    }
}

// ---------------- per-branch scan (rowptr/cursor) + dinv ----------------
__global__ void k_scan(int N) {
    int b = blockIdx.x;
    __shared__ int sh[1024];
    __shared__ int carry;
    if (threadIdx.x == 0) carry = 0;
    __syncthreads();
    for (int base = 0; base < N; base += 1024) {
        int i = base + threadIdx.x;
        int v = (i < N) ? g_deg[b][i] : 0;
        sh[threadIdx.x] = v;
        __syncthreads();
        #pragma unroll
        for (int off = 1; off < 1024; off <<= 1) {
            int t = (threadIdx.x >= off) ? sh[threadIdx.x - off] : 0;
            __syncthreads();
            sh[threadIdx.x] += t;
            __syncthreads();
        }
        if (i < N) {
            int excl = carry + sh[threadIdx.x] - v;
            g_rowptr[b][i] = excl;
            g_cursor[b][i] = excl;
        }
        __syncthreads();
        if (threadIdx.x == 1023) carry += sh[1023];
        __syncthreads();
    }
    if (threadIdx.x == 0) g_rowptr[b][N] = carry;
    for (int i = threadIdx.x; i < N; i += 1024)
        g_dinv[b][i] = rsqrtf((float)(g_deg[b][i] + 1));
}

// ---------------- CSR fill (both branches) + goff (2 tail blocks) ----------------
__global__ void k_fill(const void* ei0, const void* ei1,
                       const void* bt0, const void* bt1, int E, int N, int nbE) {
    if ((int)blockIdx.x < nbE) {
        int b = blockIdx.y;
        int e = blockIdx.x * blockDim.x + threadIdx.x;
        if (e < E) {
            const void* ei = b ? ei1 : ei0;
            int is64 = g_is64[2 * b];
            int s = idx_at(ei, e, is64);
            int d = idx_at(ei, (long long)E + e, is64);
            int pos = atomicAdd(&g_cursor[b][d], 1);
            g_col[b][pos] = s;
        }
    } else if (blockIdx.y == 0) {
        int b = blockIdx.x - nbE;
        int g = threadIdx.x;
        if (g > NG) return;
        const void* batch = b ? bt1 : bt0;
        int is64 = g_is64[2 * b + 1];
        int lo = 0, hi = N;
        while (lo < hi) {
            int mid = (lo + hi) >> 1;
            if (idx_at(batch, mid, is64) < g) lo = mid + 1; else hi = mid;
        }
        g_goff[b][g] = lo;
    }
}

// ---------------- aggregation: reads fp16 x, fp32 accum, writes fp16 agg ----------------
__global__ void k_agg() {
    int b = blockIdx.y;
    int row = blockIdx.x;
    int t = threadIdx.x;                       // 256 threads, 4 cols each
    const uint2* __restrict__ x2v = (const uint2*)g_x16[b];
    float dv = g_dinv[b][row];
    uint2 xr = __ldg(&x2v[(size_t)row * 256 + t]);
    __half2 xr0 = *(__half2*)&xr.x, xr1 = *(__half2*)&xr.y;
    float w0 = dv * dv;
    float2 f0 = __half22float2(xr0), f1 = __half22float2(xr1);
    float4 acc;
    acc.x = f0.x * w0; acc.y = f0.y * w0; acc.z = f1.x * w0; acc.w = f1.y * w0;
    int s = g_rowptr[b][row], e = g_rowptr[b][row + 1];
    for (int j = s; j < e; j++) {
        int u = g_col[b][j];
        float w = g_dinv[b][u] * dv;
        uint2 xu = __ldg(&x2v[(size_t)u * 256 + t]);
        __half2 a0 = *(__half2*)&xu.x, a1 = *(__half2*)&xu.y;
        float2 g0 = __half22float2(a0), g1 = __half22float2(a1);
        acc.x += g0.x * w; acc.y += g0.y * w; acc.z += g1.x * w; acc.w += g1.y * w;
    }
    __half2 p0 = __floats2half2_rn(acc.x, acc.y);
    __half2 p1 = __floats2half2_rn(acc.z, acc.w);
    uint2 v;
    v.x = *(uint32_t*)&p0; v.y = *(uint32_t*)&p1;
    ((uint2*)g_a16[b])[(size_t)row * 256 + t] = v;
}

// ---------------- W transpose + fp16 convert, both branches ----------------
__global__ void k_wt(const float* __restrict__ W0, const float* __restrict__ W1) {
    int b = blockIdx.z;
    const float* __restrict__ W = b ? W1 : W0;
    __shared__ float t[32][33];
    int tx = threadIdx.x, ty = threadIdx.y;
    int x = blockIdx.x * 32 + tx;
    #pragma unroll
    for (int j = 0; j < 4; j++) {
        int y = blockIdx.y * 32 + ty + j * 8;
        t[ty + j * 8][tx] = W[(size_t)y * F + x];
    }
    __syncthreads();
    int xo = blockIdx.y * 32 + tx;  // k
    #pragma unroll
    for (int j = 0; j < 4; j++) {
        int yo = blockIdx.x * 32 + ty + j * 8;  // n
        g_wh[b][(size_t)yo * F + xo] = __float2half_rn(t[tx][ty + j * 8]);
    }
}

// ---------------- fp16 HMMA GEMM: Y16 = fp16(leaky(A@W + bias)) ----------------
#define BK        64
#define NCHUNK    (F / BK)            // 16
#define ROWPAD    72                   // fp16 elems per smem row (64 data + 8 pad)
#define SA_BYTES  (128 * ROWPAD * 2)   // 18432 per tensor
#define STG_BYTES (2 * SA_BYTES)       // A, W
#define SM_TOT    (2 * STG_BYTES)      // 73728

__global__ __launch_bounds__(256)
void k_tgemm(const float* __restrict__ bias0, const float* __restrict__ bias1, int M) {
    extern __shared__ char smem[];
    uint32_t sb = smem_to_u32(smem);
    int br = blockIdx.z;
    const float* __restrict__ bias = br ? bias1 : bias0;
    const __half* __restrict__ A  = g_a16[br];
    const __half* __restrict__ Wh = g_wh[br];

    int tid = threadIdx.x;
    int wid = tid >> 5, lane = tid & 31;
    int gid = lane >> 2, tig = lane & 3;
    int warp_m = wid & 1, warp_n = wid >> 1;
    int m0 = blockIdx.y * 128;
    int n0 = blockIdx.x * 128;

    float acc[4][4][4];
    #pragma unroll
    for (int i = 0; i < 4; i++)
        #pragma unroll
        for (int j = 0; j < 4; j++)
            #pragma unroll
            for (int q = 0; q < 4; q++) acc[i][j][q] = 0.0f;

    auto load_chunk = [&](int c, int s) {
        uint32_t stg = sb + s * STG_BYTES;
        int k0 = c * BK;
        #pragma unroll
        for (int l = 0; l < 8; l++) {
            int idx = l * 256 + tid;     // 0..2047
            int tsr = idx >> 10;          // 0 A, 1 W
            int rem = idx & 1023;
            int row = rem >> 3;           // 0..127
            int c16 = rem & 7;
            const __half* gsrc;
            bool pred = true;
            if (tsr == 0) {
                int grow = m0 + row;
                pred = grow < M;
                gsrc = A + (size_t)(pred ? grow : 0) * F + k0 + c16 * 8;
            } else {
                gsrc = Wh + (size_t)(n0 + row) * F + k0 + c16 * 8;
            }
            uint32_t sdst = stg + tsr * SA_BYTES + row * (ROWPAD * 2) + c16 * 16;
            cp_async16(sdst, gsrc, pred);
        }
        cp_commit();
    };

    load_chunk(0, 0);

    for (int c = 0; c < NCHUNK; c++) {
        int s = c & 1;
        if (c + 1 < NCHUNK) {
            load_chunk(c + 1, s ^ 1);
            cp_wait<1>();
        } else {
            cp_wait<0>();
        }
        __syncthreads();

        uint32_t sa  = sb + s * STG_BYTES;
        uint32_t sbh = sa + SA_BYTES;

        #pragma unroll
        for (int ks = 0; ks < 4; ks++) {
            int kb = ks * 16;
            uint32_t bh[4][2];
            #pragma unroll
            for (int nt = 0; nt < 4; nt++) {
                int n = warp_n * 32 + nt * 8 + gid;
                uint32_t o = n * (ROWPAD * 2) + (kb + tig * 2) * 2;
                bh[nt][0] = lds32(sbh + o);
                bh[nt][1] = lds32(sbh + o + 16);
            }
            #pragma unroll
            for (int mt = 0; mt < 4; mt++) {
                int r = warp_m * 64 + mt * 16 + gid;
                uint32_t o = r * (ROWPAD * 2) + (kb + tig * 2) * 2;
                uint32_t ah[4];
                ah[0] = lds32(sa + o);
                ah[1] = lds32(sa + o + 8 * (ROWPAD * 2));
                ah[2] = lds32(sa + o + 16);
                ah[3] = lds32(sa + o + 8 * (ROWPAD * 2) + 16);
                #pragma unroll
                for (int nt = 0; nt < 4; nt++) {
                    mma16816(acc[mt][nt], ah, bh[nt]);
                }
            }
        }
        __syncthreads();
    }

    // ---- epilogue: bias + leaky, store fp16 ----
    __half* __restrict__ Y = g_y16[br];
    #pragma unroll
    for (int mt = 0; mt < 4; mt++) {
        int r0 = m0 + warp_m * 64 + mt * 16 + gid;
        #pragma unroll
        for (int nt = 0; nt < 4; nt++) {
            int col = n0 + warp_n * 32 + nt * 8 + tig * 2;
            float b0 = __ldg(&bias[col]);
            float b1 = __ldg(&bias[col + 1]);
            float* cf = acc[mt][nt];
            if (r0 < M) {
                __half2 v = __floats2half2_rn(leaky(cf[0] + b0), leaky(cf[1] + b1));
                *(__half2*)(Y + (size_t)r0 * F + col) = v;
            }
            if (r0 + 8 < M) {
                __half2 v = __floats2half2_rn(leaky(cf[2] + b0), leaky(cf[3] + b1));
                *(__half2*)(Y + (size_t)(r0 + 8) * F + col) = v;
            }
        }
    }
}

// ---------------- global mean pool (fp16 in, fp32 out), both branches ----------------
__global__ void k_pool() {
    int b = blockIdx.z;
    int g = blockIdx.y;
    int c2 = blockIdx.x * 128 + threadIdx.x;    // half2 column index, 0..511
    int s = g_goff[b][g], e = g_goff[b][g + 1];
    const __half2* __restrict__ Y2 = (const __half2*)g_y16[b];
    float2 sum = {0.0f, 0.0f};
    for (int r = s; r < e; r++) {
        float2 v = __half22float2(Y2[(size_t)r * (F / 2) + c2]);
        sum.x += v.x; sum.y += v.y;
    }
    float inv = 1.0f / fmaxf((float)(e - s), 1.0f);
    g_pool[b][g * F + 2 * c2]     = sum.x * inv;
    g_pool[b][g * F + 2 * c2 + 1] = sum.y * inv;
}

// ---------------- fc, both branches ----------------
__global__ void k_fc(const float* __restrict__ Wf0, const float* __restrict__ bf0,
                     const float* __restrict__ Wf1, const float* __restrict__ bf1) {
    int b = blockIdx.y;
    const float* __restrict__ Wf = b ? Wf1 : Wf0;
    const float* __restrict__ bf = b ? bf1 : bf0;
    __shared__ float p[F];
    int g = blockIdx.x, t = threadIdx.x;
    for (int k = t; k < F; k += 128) p[k] = g_pool[b][g * F + k];
    __syncthreads();
    float acc = 0.0f;
    #pragma unroll 8
    for (int k = 0; k < F; k++) acc += p[k] * Wf[k * DD + t];
    acc += bf[t];
    g_z[b][g * DD + t] = leaky(acc);
}

// ---------------- final ----------------
__global__ void k_final(const float* __restrict__ fW, const float* __restrict__ fb,
                        float* __restrict__ out) {
    __shared__ float sh[256];
    int g = blockIdx.x, t = threadIdx.x;
    float v;
    if (t < DD) v = g_z[0][g * DD + t] * fW[t];
    else        v = g_z[1][g * DD + (t - DD)] * fW[t];
    sh[t] = v;
    __syncthreads();
    #pragma unroll
    for (int s = 128; s > 0; s >>= 1) {
        if (t < s) sh[t] += sh[t + s];
        __syncthreads();
    }
    if (t == 0) out[g] = sh[0] + fb[0];
}

// ---------------- host launcher ----------------
extern "C" void kernel_launch(void* const* d_in, const int* in_sizes, int n_in,
                              void* d_out, int out_size) {
    const float* x1  = (const float*)d_in[0];
    const void*  ei1 = d_in[1];
    const void*  bt1 = d_in[2];
    const float* x2  = (const float*)d_in[3];
    const void*  ei2 = d_in[4];
    const void*  bt2 = d_in[5];
    int wb = n_in - 10;
    const float* c1W = (const float*)d_in[wb + 0];
    const float* c1b = (const float*)d_in[wb + 1];
    const float* f1W = (const float*)d_in[wb + 2];
    const float* f1b = (const float*)d_in[wb + 3];
    const float* c2W = (const float*)d_in[wb + 4];
    const float* c2b = (const float*)d_in[wb + 5];
    const float* f2W = (const float*)d_in[wb + 6];
    const float* f2b = (const float*)d_in[wb + 7];
    const float* fW  = (const float*)d_in[wb + 8];
    const float* fb  = (const float*)d_in[wb + 9];
    float* out = (float*)d_out;

    int N = in_sizes[0] / F;
    int E = in_sizes[1] / 2;

    cudaFuncSetAttribute(k_tgemm, cudaFuncAttributeMaxDynamicSharedMemorySize, SM_TOT);

    int zb = (2 * MAXN + 255) / 256;
    int total4 = N * (F / 4);                    // float4 elems per branch
    int cvb = (2 * total4 + 255) / 256;          // conversion blocks (both branches)
    k_pre<<<4 + zb + cvb, 256>>>((const unsigned int*)ei1, (const unsigned int*)bt1,
                                 (const unsigned int*)ei2, (const unsigned int*)bt2,
                                 2 * E, N, 2 * E, N, x1, x2, zb, total4);
    int nbE = (E + 255) / 256;
    k_deg<<<dim3(nbE, 2), 256>>>(ei1, ei2, E);
    k_scan<<<2, 1024>>>(N);
    k_fill<<<dim3(nbE + 2, 2), 256>>>(ei1, ei2, bt1, bt2, E, N, nbE);
    k_agg<<<dim3(N, 2), 256>>>();
    k_wt<<<dim3(F / 32, F / 32, 2), dim3(32, 8)>>>(c1W, c2W);
    k_tgemm<<<dim3(F / 128, (N + 127) / 128, 2), 256, SM_TOT>>>(c1b, c2b, N);
    k_pool<<<dim3(F / 256, NG, 2), 128>>>();
    k_fc<<<dim3(NG, 2), DD>>>(f1W, f1b, f2W, f2b);
    k_final<<<NG, 256>>>(fW, fb, out);
}

// round 8
// speedup vs baseline: 4.1564x; 1.0048x over previous
#include <cuda_runtime.h>
#include <cuda_fp16.h>
#include <cstdint>
#include <math.h>

#define F    1024
#define MAXN 10000
#define MAXE 80000
#define NG   64
#define DD   128

// ---------------- static device scratch ----------------
__device__ __half g_x16[2][(size_t)MAXN * F];    // fp16(x)
__device__ __half g_y16[2][(size_t)MAXN * F];    // fp16(leaky(agg@W + b))
__device__ __half g_a16[2][(size_t)MAXN * F];    // fp16(agg)
__device__ __half g_wh[2][(size_t)F * F];        // fp16(W^T)  [n][k]
__device__ int   g_deg[2][MAXN];
__device__ float g_dinv[2][MAXN];
__device__ int   g_rowptr[2][MAXN + 1];
__device__ int   g_cursor[2][MAXN];
__device__ int   g_col[2][MAXE];
__device__ int   g_goff[2][NG + 1];
__device__ float g_pool[2][NG * F];
__device__ float g_z[2][NG * DD];
__device__ int   g_is64[4];   // 0: edge b0, 1: batch b0, 2: edge b1, 3: batch b1

__device__ __forceinline__ float leaky(float v) { return v >= 0.0f ? v : 0.01f * v; }

__device__ __forceinline__ int idx_at(const void* p, long long i, int is64) {
    return is64 ? (int)(((const long long*)p)[i]) : ((const int*)p)[i];
}

// ---------------- low-level helpers ----------------
__device__ __forceinline__ uint32_t smem_to_u32(const void* smem_ptr) {
    uint32_t addr;
    asm("{ .reg .u64 tmp; cvta.to.shared.u64 tmp, %1; cvt.u32.u64 %0, tmp; }"
        : "=r"(addr) : "l"(smem_ptr));
    return addr;
}
__device__ __forceinline__ void cp_async16(uint32_t dst, const void* src, bool p) {
    asm volatile("cp.async.cg.shared.global [%0], [%1], 16, %2;"
                 :: "r"(dst), "l"(src), "r"(p ? 16u : 0u) : "memory");
}
__device__ __forceinline__ void cp_commit() {
    asm volatile("cp.async.commit_group;" ::: "memory");
}
template <int N>
__device__ __forceinline__ void cp_wait() {
    asm volatile("cp.async.wait_group %0;" :: "n"(N) : "memory");
}
__device__ __forceinline__ uint32_t lds32(uint32_t addr) {
    uint32_t v;
    asm volatile("ld.shared.b32 %0, [%1];" : "=r"(v) : "r"(addr));
    return v;
}
__device__ __forceinline__ void mma16816(float* c, const uint32_t* a, const uint32_t* b) {
    asm volatile(
        "mma.sync.aligned.m16n8k16.row.col.f32.f16.f16.f32 "
        "{%0,%1,%2,%3}, {%4,%5,%6,%7}, {%8,%9}, {%0,%1,%2,%3};"
        : "+f"(c[0]), "+f"(c[1]), "+f"(c[2]), "+f"(c[3])
        : "r"(a[0]), "r"(a[1]), "r"(a[2]), "r"(a[3]), "r"(b[0]), "r"(b[1]));
}

// ---------------- fused: dtype detect + deg zeroing + x->fp16 convert ----------------
__global__ void k_pre(const unsigned int* p0, const unsigned int* p1,
                      const unsigned int* p2, const unsigned int* p3,
                      int nw0, int nw1, int nw2, int nw3,
                      const float* __restrict__ x0, const float* __restrict__ x1,
                      int zb, int total4) {
    if (blockIdx.x < 4) {
        const unsigned int* p; int nw;
        if (blockIdx.x == 0)      { p = p0; nw = nw0; }
        else if (blockIdx.x == 1) { p = p1; nw = nw1; }
        else if (blockIdx.x == 2) { p = p2; nw = nw2; }
        else                      { p = p3; nw = nw3; }
        int start = nw > 4096 ? nw - 4096 : 0;
        __shared__ unsigned int sh[256];
        unsigned int acc = 0;
        for (int i = start + threadIdx.x; i < nw; i += 256)
            if (i & 1) acc |= p[i];
        sh[threadIdx.x] = acc;
        __syncthreads();
        for (int s = 128; s > 0; s >>= 1) {
            if (threadIdx.x < s) sh[threadIdx.x] |= sh[threadIdx.x + s];
            __syncthreads();
        }
        if (threadIdx.x == 0) g_is64[blockIdx.x] = (sh[0] == 0u) ? 1 : 0;
    } else if ((int)blockIdx.x < 4 + zb) {
        int i = (blockIdx.x - 4) * 256 + threadIdx.x;
        if (i < 2 * MAXN) ((int*)g_deg)[i] = 0;
    } else {
        long long i = (long long)(blockIdx.x - 4 - zb) * 256 + threadIdx.x;
        int b = (i >= total4);
        long long li = b ? i - total4 : i;
        if (li < total4) {
            const float4* __restrict__ x4 = (const float4*)(b ? x1 : x0);
            float4 v = __ldg(&x4[li]);
            __half2 h0 = __floats2half2_rn(v.x, v.y);
            __half2 h1 = __floats2half2_rn(v.z, v.w);
            uint2 u;
            u.x = *(uint32_t*)&h0; u.y = *(uint32_t*)&h1;
            ((uint2*)g_x16[b])[li] = u;
        }
    }
}

// ---------------- degree histogram, both branches ----------------
__global__ void k_deg(const void* ei0, const void* ei1, int E) {
    int b = blockIdx.y;
    int e = blockIdx.x * blockDim.x + threadIdx.x;
    if (e < E) {
        const void* ei = b ? ei1 : ei0;
        int is64 = g_is64[2 * b];
        atomicAdd(&g_deg[b][idx_at(ei, (long long)E + e, is64)], 1);
    }
}

// ---------------- per-branch scan (warp-shuffle) + dinv ----------------
__global__ void k_scan(int N) {
    int b = blockIdx.x;
    __shared__ int wsum[32];
    __shared__ int carry;
    int lane = threadIdx.x & 31, wid = threadIdx.x >> 5;
    if (threadIdx.x == 0) carry = 0;
    __syncthreads();
    for (int base = 0; base < N; base += 1024) {
        int i = base + threadIdx.x;
        int v = (i < N) ? g_deg[b][i] : 0;
        // warp inclusive scan
        int sc = v;
        #pragma unroll
        for (int off = 1; off < 32; off <<= 1) {
            int t = __shfl_up_sync(0xFFFFFFFF, sc, off);
            if (lane >= off) sc += t;
        }
        if (lane == 31) wsum[wid] = sc;
        __syncthreads();
        if (wid == 0) {
            int ws = (lane < 32) ? wsum[lane] : 0;
            #pragma unroll
            for (int off = 1; off < 32; off <<= 1) {
                int t = __shfl_up_sync(0xFFFFFFFF, ws, off);
                if (lane >= off) ws += t;
            }
            wsum[lane] = ws;
        }
        __syncthreads();
        int incl = sc + (wid > 0 ? wsum[wid - 1] : 0) + carry;
        if (i < N) {
            g_rowptr[b][i] = incl - v;
            g_cursor[b][i] = incl - v;
        }
        __syncthreads();
        if (threadIdx.x == 1023) carry = incl;
        __syncthreads();
    }
    if (threadIdx.x == 0) g_rowptr[b][N] = carry;
    for (int i = threadIdx.x; i < N; i += 1024)
        g_dinv[b][i] = rsqrtf((float)(g_deg[b][i] + 1));
}

// ---------------- CSR fill (both branches) + goff (2 tail blocks) ----------------
__global__ void k_fill(const void* ei0, const void* ei1,
                       const void* bt0, const void* bt1, int E, int N, int nbE) {
    if ((int)blockIdx.x < nbE) {
        int b = blockIdx.y;
        int e = blockIdx.x * blockDim.x + threadIdx.x;
        if (e < E) {
            const void* ei = b ? ei1 : ei0;
            int is64 = g_is64[2 * b];
            int s = idx_at(ei, e, is64);
            int d = idx_at(ei, (long long)E + e, is64);
            int pos = atomicAdd(&g_cursor[b][d], 1);
            g_col[b][pos] = s;
        }
    } else if (blockIdx.y == 0) {
        int b = blockIdx.x - nbE;
        int g = threadIdx.x;
        if (g > NG) return;
        const void* batch = b ? bt1 : bt0;
        int is64 = g_is64[2 * b + 1];
        int lo = 0, hi = N;
        while (lo < hi) {
            int mid = (lo + hi) >> 1;
            if (idx_at(batch, mid, is64) < g) lo = mid + 1; else hi = mid;
        }
        g_goff[b][g] = lo;
    }
}

// ---------------- aggregation: 4-way index prefetch for MLP ----------------
__global__ void k_agg() {
    int b = blockIdx.y;
    int row = blockIdx.x;
    int t = threadIdx.x;                       // 256 threads, 4 cols each
    const uint2* __restrict__ x2v = (const uint2*)g_x16[b];
    const int* __restrict__ col = g_col[b];
    const float* __restrict__ dinv = g_dinv[b];
    float dv = dinv[row];
    uint2 xr = __ldg(&x2v[(size_t)row * 256 + t]);
    __half2 xr0 = *(__half2*)&xr.x, xr1 = *(__half2*)&xr.y;
    float w0 = dv * dv;
    float2 f0 = __half22float2(xr0), f1 = __half22float2(xr1);
    float4 acc;
    acc.x = f0.x * w0; acc.y = f0.y * w0; acc.z = f1.x * w0; acc.w = f1.y * w0;
    int s = g_rowptr[b][row], e = g_rowptr[b][row + 1];
    int j = s;
    for (; j + 4 <= e; j += 4) {
        int u0 = col[j], u1 = col[j + 1], u2 = col[j + 2], u3 = col[j + 3];
        float wa = dinv[u0] * dv, wb = dinv[u1] * dv;
        float wc = dinv[u2] * dv, wd = dinv[u3] * dv;
        uint2 v0 = __ldg(&x2v[(size_t)u0 * 256 + t]);
        uint2 v1 = __ldg(&x2v[(size_t)u1 * 256 + t]);
        uint2 v2 = __ldg(&x2v[(size_t)u2 * 256 + t]);
        uint2 v3 = __ldg(&x2v[(size_t)u3 * 256 + t]);
        float2 a0 = __half22float2(*(__half2*)&v0.x), a1 = __half22float2(*(__half2*)&v0.y);
        acc.x += a0.x * wa; acc.y += a0.y * wa; acc.z += a1.x * wa; acc.w += a1.y * wa;
        float2 b0 = __half22float2(*(__half2*)&v1.x), b1 = __half22float2(*(__half2*)&v1.y);
        acc.x += b0.x * wb; acc.y += b0.y * wb; acc.z += b1.x * wb; acc.w += b1.y * wb;
        float2 c0 = __half22float2(*(__half2*)&v2.x), c1 = __half22float2(*(__half2*)&v2.y);
        acc.x += c0.x * wc; acc.y += c0.y * wc; acc.z += c1.x * wc; acc.w += c1.y * wc;
        float2 d0 = __half22float2(*(__half2*)&v3.x), d1 = __half22float2(*(__half2*)&v3.y);
        acc.x += d0.x * wd; acc.y += d0.y * wd; acc.z += d1.x * wd; acc.w += d1.y * wd;
    }
    for (; j < e; j++) {
        int u = col[j];
        float w = dinv[u] * dv;
        uint2 xu = __ldg(&x2v[(size_t)u * 256 + t]);
        float2 g0 = __half22float2(*(__half2*)&xu.x), g1 = __half22float2(*(__half2*)&xu.y);
        acc.x += g0.x * w; acc.y += g0.y * w; acc.z += g1.x * w; acc.w += g1.y * w;
    }
    __half2 p0 = __floats2half2_rn(acc.x, acc.y);
    __half2 p1 = __floats2half2_rn(acc.z, acc.w);
    uint2 v;
    v.x = *(uint32_t*)&p0; v.y = *(uint32_t*)&p1;
    ((uint2*)g_a16[b])[(size_t)row * 256 + t] = v;
}

// ---------------- W transpose + fp16 convert, both branches ----------------
__global__ void k_wt(const float* __restrict__ W0, const float* __restrict__ W1) {
    int b = blockIdx.z;
    const float* __restrict__ W = b ? W1 : W0;
    __shared__ float t[32][33];
    int tx = threadIdx.x, ty = threadIdx.y;
    int x = blockIdx.x * 32 + tx;
    #pragma unroll
    for (int j = 0; j < 4; j++) {
        int y = blockIdx.y * 32 + ty + j * 8;
        t[ty + j * 8][tx] = W[(size_t)y * F + x];
    }
    __syncthreads();
    int xo = blockIdx.y * 32 + tx;  // k
    #pragma unroll
    for (int j = 0; j < 4; j++) {
        int yo = blockIdx.x * 32 + ty + j * 8;  // n
        g_wh[b][(size_t)yo * F + xo] = __float2half_rn(t[tx][ty + j * 8]);
    }
}

// ---------------- fp16 HMMA GEMM: Y16 = fp16(leaky(A@W + bias)) ----------------
#define BK        64
#define NCHUNK    (F / BK)            // 16
#define ROWPAD    72                   // fp16 elems per smem row (64 data + 8 pad)
#define SA_BYTES  (128 * ROWPAD * 2)   // 18432 per tensor
#define STG_BYTES (2 * SA_BYTES)       // A, W
#define SM_TOT    (2 * STG_BYTES)      // 73728

__global__ __launch_bounds__(256, 2)
void k_tgemm(const float* __restrict__ bias0, const float* __restrict__ bias1, int M) {
    extern __shared__ char smem[];
    uint32_t sb = smem_to_u32(smem);
    int br = blockIdx.z;
    const float* __restrict__ bias = br ? bias1 : bias0;
    const __half* __restrict__ A  = g_a16[br];
    const __half* __restrict__ Wh = g_wh[br];

    int tid = threadIdx.x;
    int wid = tid >> 5, lane = tid & 31;
    int gid = lane >> 2, tig = lane & 3;
    int warp_m = wid & 1, warp_n = wid >> 1;
    int m0 = blockIdx.y * 128;
    int n0 = blockIdx.x * 128;

    float acc[4][4][4];
    #pragma unroll
    for (int i = 0; i < 4; i++)
        #pragma unroll
        for (int j = 0; j < 4; j++)
            #pragma unroll
            for (int q = 0; q < 4; q++) acc[i][j][q] = 0.0f;

    auto load_chunk = [&](int c, int s) {
        uint32_t stg = sb + s * STG_BYTES;
        int k0 = c * BK;
        #pragma unroll
        for (int l = 0; l < 8; l++) {
            int idx = l * 256 + tid;     // 0..2047
            int tsr = idx >> 10;          // 0 A, 1 W
            int rem = idx & 1023;
            int row = rem >> 3;           // 0..127
            int c16 = rem & 7;
            const __half* gsrc;
            bool pred = true;
            if (tsr == 0) {
                int grow = m0 + row;
                pred = grow < M;
                gsrc = A + (size_t)(pred ? grow : 0) * F + k0 + c16 * 8;
            } else {
                gsrc = Wh + (size_t)(n0 + row) * F + k0 + c16 * 8;
            }
            uint32_t sdst = stg + tsr * SA_BYTES + row * (ROWPAD * 2) + c16 * 16;
            cp_async16(sdst, gsrc, pred);
        }
        cp_commit();
    };

    load_chunk(0, 0);

    for (int c = 0; c < NCHUNK; c++) {
        int s = c & 1;
        if (c + 1 < NCHUNK) {
            load_chunk(c + 1, s ^ 1);
            cp_wait<1>();
        } else {
            cp_wait<0>();
        }
        __syncthreads();

        uint32_t sa  = sb + s * STG_BYTES;
        uint32_t sbh = sa + SA_BYTES;

        #pragma unroll
        for (int ks = 0; ks < 4; ks++) {
            int kb = ks * 16;
            uint32_t bh[4][2];
            #pragma unroll
            for (int nt = 0; nt < 4; nt++) {
                int n = warp_n * 32 + nt * 8 + gid;
                uint32_t o = n * (ROWPAD * 2) + (kb + tig * 2) * 2;
                bh[nt][0] = lds32(sbh + o);
                bh[nt][1] = lds32(sbh + o + 16);
            }
            #pragma unroll
            for (int mt = 0; mt < 4; mt++) {
                int r = warp_m * 64 + mt * 16 + gid;
                uint32_t o = r * (ROWPAD * 2) + (kb + tig * 2) * 2;
                uint32_t ah[4];
                ah[0] = lds32(sa + o);
                ah[1] = lds32(sa + o + 8 * (ROWPAD * 2));
                ah[2] = lds32(sa + o + 16);
                ah[3] = lds32(sa + o + 8 * (ROWPAD * 2) + 16);
                #pragma unroll
                for (int nt = 0; nt < 4; nt++) {
                    mma16816(acc[mt][nt], ah, bh[nt]);
                }
            }
        }
        __syncthreads();
    }

    // ---- epilogue: bias + leaky, store fp16 ----
    __half* __restrict__ Y = g_y16[br];
    #pragma unroll
    for (int mt = 0; mt < 4; mt++) {
        int r0 = m0 + warp_m * 64 + mt * 16 + gid;
        #pragma unroll
        for (int nt = 0; nt < 4; nt++) {
            int col = n0 + warp_n * 32 + nt * 8 + tig * 2;
            float b0 = __ldg(&bias[col]);
            float b1 = __ldg(&bias[col + 1]);
            float* cf = acc[mt][nt];
            if (r0 < M) {
                __half2 v = __floats2half2_rn(leaky(cf[0] + b0), leaky(cf[1] + b1));
                *(__half2*)(Y + (size_t)r0 * F + col) = v;
            }
            if (r0 + 8 < M) {
                __half2 v = __floats2half2_rn(leaky(cf[2] + b0), leaky(cf[3] + b1));
                *(__half2*)(Y + (size_t)(r0 + 8) * F + col) = v;
            }
        }
    }
}

// ---------------- global mean pool (fp16 in, fp32 out), both branches ----------------
__global__ void k_pool() {
    int b = blockIdx.z;
    int g = blockIdx.y;
    int c2 = blockIdx.x * 128 + threadIdx.x;    // half2 column index
    int s = g_goff[b][g], e = g_goff[b][g + 1];
    const __half2* __restrict__ Y2 = (const __half2*)g_y16[b];
    float2 sum = {0.0f, 0.0f};
    for (int r = s; r < e; r++) {
        float2 v = __half22float2(Y2[(size_t)r * (F / 2) + c2]);
        sum.x += v.x; sum.y += v.y;
    }
    float inv = 1.0f / fmaxf((float)(e - s), 1.0f);
    g_pool[b][g * F + 2 * c2]     = sum.x * inv;
    g_pool[b][g * F + 2 * c2 + 1] = sum.y * inv;
}

// ---------------- fc, both branches ----------------
__global__ void k_fc(const float* __restrict__ Wf0, const float* __restrict__ bf0,
                     const float* __restrict__ Wf1, const float* __restrict__ bf1) {
    int b = blockIdx.y;
    const float* __restrict__ Wf = b ? Wf1 : Wf0;
    const float* __restrict__ bf = b ? bf1 : bf0;
    __shared__ float p[F];
    int g = blockIdx.x, t = threadIdx.x;
    for (int k = t; k < F; k += 128) p[k] = g_pool[b][g * F + k];
    __syncthreads();
    float acc = 0.0f;
    #pragma unroll 8
    for (int k = 0; k < F; k++) acc += p[k] * Wf[k * DD + t];
    acc += bf[t];
    g_z[b][g * DD + t] = leaky(acc);
}

// ---------------- final ----------------
__global__ void k_final(const float* __restrict__ fW, const float* __restrict__ fb,
                        float* __restrict__ out) {
    __shared__ float sh[256];
    int g = blockIdx.x, t = threadIdx.x;
    float v;
    if (t < DD) v = g_z[0][g * DD + t] * fW[t];
    else        v = g_z[1][g * DD + (t - DD)] * fW[t];
    sh[t] = v;
    __syncthreads();
    #pragma unroll
    for (int s = 128; s > 0; s >>= 1) {
        if (t < s) sh[t] += sh[t + s];
        __syncthreads();
    }
    if (t == 0) out[g] = sh[0] + fb[0];
}

// ---------------- host launcher ----------------
extern "C" void kernel_launch(void* const* d_in, const int* in_sizes, int n_in,
                              void* d_out, int out_size) {
    const float* x1  = (const float*)d_in[0];
    const void*  ei1 = d_in[1];
    const void*  bt1 = d_in[2];
    const float* x2  = (const float*)d_in[3];
    const void*  ei2 = d_in[4];
    const void*  bt2 = d_in[5];
    int wb = n_in - 10;
    const float* c1W = (const float*)d_in[wb + 0];
    const float* c1b = (const float*)d_in[wb + 1];
    const float* f1W = (const float*)d_in[wb + 2];
    const float* f1b = (const float*)d_in[wb + 3];
    const float* c2W = (const float*)d_in[wb + 4];
    const float* c2b = (const float*)d_in[wb + 5];
    const float* f2W = (const float*)d_in[wb + 6];
    const float* f2b = (const float*)d_in[wb + 7];
    const float* fW  = (const float*)d_in[wb + 8];
    const float* fb  = (const float*)d_in[wb + 9];
    float* out = (float*)d_out;

    int N = in_sizes[0] / F;
    int E = in_sizes[1] / 2;

    cudaFuncSetAttribute(k_tgemm, cudaFuncAttributeMaxDynamicSharedMemorySize, SM_TOT);

    int zb = (2 * MAXN + 255) / 256;
    int total4 = N * (F / 4);
    int cvb = (2 * total4 + 255) / 256;
    k_pre<<<4 + zb + cvb, 256>>>((const unsigned int*)ei1, (const unsigned int*)bt1,
                                 (const unsigned int*)ei2, (const unsigned int*)bt2,
                                 2 * E, N, 2 * E, N, x1, x2, zb, total4);
    int nbE = (E + 255) / 256;
    k_deg<<<dim3(nbE, 2), 256>>>(ei1, ei2, E);
    k_scan<<<2, 1024>>>(N);
    k_fill<<<dim3(nbE + 2, 2), 256>>>(ei1, ei2, bt1, bt2, E, N, nbE);
    k_agg<<<dim3(N, 2), 256>>>();
    k_wt<<<dim3(F / 32, F / 32, 2), dim3(32, 8)>>>(c1W, c2W);
    k_tgemm<<<dim3(F / 128, (N + 127) / 128, 2), 256, SM_TOT>>>(c1b, c2b, N);
    k_pool<<<dim3(F / 256, NG, 2), 128>>>();
    k_fc<<<dim3(NG, 2), DD>>>(f1W, f1b, f2W, f2b);
    k_final<<<NG, 256>>>(fW, fb, out);
}

// round 9
// speedup vs baseline: 4.1655x; 1.0022x over previous
#include <cuda_runtime.h>
#include <cuda_fp16.h>
#include <cstdint>
#include <math.h>

#define F    1024
#define MAXN 10000
#define MAXE 80000
#define NG   64
#define DD   128

// ---------------- static device scratch ----------------
__device__ __half g_x16[2][(size_t)MAXN * F];    // fp16(x)
__device__ __half g_y16[2][(size_t)MAXN * F];    // fp16(leaky(agg@W + b))
__device__ __half g_a16[2][(size_t)MAXN * F];    // fp16(agg)
__device__ __half g_wh[2][(size_t)F * F];        // fp16(W^T)  [n][k]
__device__ int   g_deg[2][MAXN];
__device__ float g_dinv[2][MAXN];
__device__ int   g_rowptr[2][MAXN + 1];
__device__ int   g_cursor[2][MAXN];
__device__ int   g_col[2][MAXE];
__device__ int   g_goff[2][NG + 1];
__device__ float g_z[2][NG * DD];
__device__ int   g_is64[4];   // 0: edge b0, 1: batch b0, 2: edge b1, 3: batch b1

__device__ __forceinline__ float leaky(float v) { return v >= 0.0f ? v : 0.01f * v; }

__device__ __forceinline__ int idx_at(const void* p, long long i, int is64) {
    return is64 ? (int)(((const long long*)p)[i]) : ((const int*)p)[i];
}

// ---------------- low-level helpers ----------------
__device__ __forceinline__ uint32_t smem_to_u32(const void* smem_ptr) {
    uint32_t addr;
    asm("{ .reg .u64 tmp; cvta.to.shared.u64 tmp, %1; cvt.u32.u64 %0, tmp; }"
        : "=r"(addr) : "l"(smem_ptr));
    return addr;
}
__device__ __forceinline__ void cp_async16(uint32_t dst, const void* src, bool p) {
    asm volatile("cp.async.cg.shared.global [%0], [%1], 16, %2;"
                 :: "r"(dst), "l"(src), "r"(p ? 16u : 0u) : "memory");
}
__device__ __forceinline__ void cp_commit() {
    asm volatile("cp.async.commit_group;" ::: "memory");
}
template <int N>
__device__ __forceinline__ void cp_wait() {
    asm volatile("cp.async.wait_group %0;" :: "n"(N) : "memory");
}
__device__ __forceinline__ uint32_t lds32(uint32_t addr) {
    uint32_t v;
    asm volatile("ld.shared.b32 %0, [%1];" : "=r"(v) : "r"(addr));
    return v;
}
__device__ __forceinline__ void mma16816(float* c, const uint32_t* a, const uint32_t* b) {
    asm volatile(
        "mma.sync.aligned.m16n8k16.row.col.f32.f16.f16.f32 "
        "{%0,%1,%2,%3}, {%4,%5,%6,%7}, {%8,%9}, {%0,%1,%2,%3};"
        : "+f"(c[0]), "+f"(c[1]), "+f"(c[2]), "+f"(c[3])
        : "r"(a[0]), "r"(a[1]), "r"(a[2]), "r"(a[3]), "r"(b[0]), "r"(b[1]));
}

// ---------------- k_pre: dtype detect (tail-scan) + deg zeroing ----------------
__global__ void k_pre(const unsigned int* p0, const unsigned int* p1,
                      const unsigned int* p2, const unsigned int* p3,
                      int nw0, int nw1, int nw2, int nw3) {
    if (blockIdx.x < 4) {
        const unsigned int* p; int nw;
        if (blockIdx.x == 0)      { p = p0; nw = nw0; }
        else if (blockIdx.x == 1) { p = p1; nw = nw1; }
        else if (blockIdx.x == 2) { p = p2; nw = nw2; }
        else                      { p = p3; nw = nw3; }
        int start = nw > 4096 ? nw - 4096 : 0;
        __shared__ unsigned int sh[256];
        unsigned int acc = 0;
        for (int i = start + threadIdx.x; i < nw; i += 256)
            if (i & 1) acc |= p[i];
        sh[threadIdx.x] = acc;
        __syncthreads();
        for (int s = 128; s > 0; s >>= 1) {
            if (threadIdx.x < s) sh[threadIdx.x] |= sh[threadIdx.x + s];
            __syncthreads();
        }
        if (threadIdx.x == 0) g_is64[blockIdx.x] = (sh[0] == 0u) ? 1 : 0;
    } else {
        int i = (blockIdx.x - 4) * 256 + threadIdx.x;
        if (i < 2 * MAXN) ((int*)g_deg)[i] = 0;
    }
}

// ---------------- degree histogram, both branches ----------------
__global__ void k_deg(const void* ei0, const void* ei1, int E) {
    int b = blockIdx.y;
    int e = blockIdx.x * blockDim.x + threadIdx.x;
    if (e < E) {
        const void* ei = b ? ei1 : ei0;
        int is64 = g_is64[2 * b];
        atomicAdd(&g_deg[b][idx_at(ei, (long long)E + e, is64)], 1);
    }
}

// ---------------- k_mid mega-kernel (1024 threads/block) ----------------
// blocks [0,2): scan+dinv per branch
// blocks [2, 2+cvb): x -> fp16 convert (both branches, float4 per thread)
// blocks [2+cvb, ...): W transpose+convert, 4x 32x32 tiles per block
__global__ __launch_bounds__(1024)
void k_mid(const float* __restrict__ x0, const float* __restrict__ x1,
           const float* __restrict__ W0, const float* __restrict__ W1,
           int N, int cvb, int total4) {
    __shared__ float smem_t[4][32][33];          // wt path
    __shared__ int wsum[32];                     // scan path
    __shared__ int carry;
    int bx = blockIdx.x;
    int tid = threadIdx.x;

    if (bx < 2) {
        // ---- exclusive scan of deg -> rowptr/cursor, + dinv ----
        int b = bx;
        int lane = tid & 31, wid = tid >> 5;
        if (tid == 0) carry = 0;
        int v_next = (tid < N) ? g_deg[b][tid] : 0;
        __syncthreads();
        for (int base = 0; base < N; base += 1024) {
            int v = v_next;
            int i2 = base + 1024 + tid;
            v_next = (i2 < N) ? g_deg[b][i2] : 0;    // prefetch next tile
            int sc = v;
            #pragma unroll
            for (int off = 1; off < 32; off <<= 1) {
                int t = __shfl_up_sync(0xFFFFFFFF, sc, off);
                if (lane >= off) sc += t;
            }
            if (lane == 31) wsum[wid] = sc;
            __syncthreads();
            if (wid == 0) {
                int ws = wsum[lane];
                #pragma unroll
                for (int off = 1; off < 32; off <<= 1) {
                    int t = __shfl_up_sync(0xFFFFFFFF, ws, off);
                    if (lane >= off) ws += t;
                }
                wsum[lane] = ws;
            }
            __syncthreads();
            int incl = sc + (wid > 0 ? wsum[wid - 1] : 0) + carry;
            int i = base + tid;
            if (i < N) {
                g_rowptr[b][i] = incl - v;
                g_cursor[b][i] = incl - v;
            }
            __syncthreads();
            if (tid == 1023) carry = incl;
            __syncthreads();
        }
        if (tid == 0) g_rowptr[b][N] = carry;
        for (int i = tid; i < N; i += 1024)
            g_dinv[b][i] = rsqrtf((float)(g_deg[b][i] + 1));
    } else if (bx < 2 + cvb) {
        // ---- x -> fp16 (both branches), 1 float4 per thread ----
        long long i = (long long)(bx - 2) * 1024 + tid;
        int b = (i >= total4);
        long long li = b ? i - total4 : i;
        if (li < total4) {
            const float4* __restrict__ x4 = (const float4*)(b ? x1 : x0);
            float4 v = __ldg(&x4[li]);
            __half2 h0 = __floats2half2_rn(v.x, v.y);
            __half2 h1 = __floats2half2_rn(v.z, v.w);
            uint2 u;
            u.x = *(uint32_t*)&h0; u.y = *(uint32_t*)&h1;
            ((uint2*)g_x16[b])[li] = u;
        }
    } else {
        // ---- W transpose + fp16: 4 tiles of 32x32 per block ----
        int q = tid >> 8;                 // quarter 0..3
        int qt = tid & 255;
        int tileid = (bx - 2 - cvb) * 4 + q;   // over (F/32)*(F/32)*2 = 2048
        if (tileid < 2048) {
            int b = tileid >> 10;
            int rem = tileid & 1023;
            int bxt = rem & 31;           // x tile (col block of W)
            int byt = rem >> 5;           // y tile (row block of W)
            const float* __restrict__ W = b ? W1 : W0;
            int tx = qt & 31, ty = qt >> 5;   // 32 x 8
            int x = bxt * 32 + tx;
            #pragma unroll
            for (int j = 0; j < 4; j++) {
                int y = byt * 32 + ty + j * 8;
                smem_t[q][ty + j * 8][tx] = W[(size_t)y * F + x];
            }
            __syncthreads();
            int xo = byt * 32 + tx;       // k
            #pragma unroll
            for (int j = 0; j < 4; j++) {
                int yo = bxt * 32 + ty + j * 8;  // n
                g_wh[b][(size_t)yo * F + xo] = __float2half_rn(smem_t[q][tx][ty + j * 8]);
            }
        }
    }
}

// ---------------- CSR fill (both branches) + goff (2 tail blocks) ----------------
__global__ void k_fill(const void* ei0, const void* ei1,
                       const void* bt0, const void* bt1, int E, int N, int nbE) {
    if ((int)blockIdx.x < nbE) {
        int b = blockIdx.y;
        int e = blockIdx.x * blockDim.x + threadIdx.x;
        if (e < E) {
            const void* ei = b ? ei1 : ei0;
            int is64 = g_is64[2 * b];
            int s = idx_at(ei, e, is64);
            int d = idx_at(ei, (long long)E + e, is64);
            int pos = atomicAdd(&g_cursor[b][d], 1);
            g_col[b][pos] = s;
        }
    } else if (blockIdx.y == 0) {
        int b = blockIdx.x - nbE;
        int g = threadIdx.x;
        if (g > NG) return;
        const void* batch = b ? bt1 : bt0;
        int is64 = g_is64[2 * b + 1];
        int lo = 0, hi = N;
        while (lo < hi) {
            int mid = (lo + hi) >> 1;
            if (idx_at(batch, mid, is64) < g) lo = mid + 1; else hi = mid;
        }
        g_goff[b][g] = lo;
    }
}

// ---------------- aggregation: 4-way index prefetch for MLP ----------------
__global__ void k_agg() {
    int b = blockIdx.y;
    int row = blockIdx.x;
    int t = threadIdx.x;                       // 256 threads, 4 cols each
    const uint2* __restrict__ x2v = (const uint2*)g_x16[b];
    const int* __restrict__ col = g_col[b];
    const float* __restrict__ dinv = g_dinv[b];
    float dv = dinv[row];
    uint2 xr = __ldg(&x2v[(size_t)row * 256 + t]);
    __half2 xr0 = *(__half2*)&xr.x, xr1 = *(__half2*)&xr.y;
    float w0 = dv * dv;
    float2 f0 = __half22float2(xr0), f1 = __half22float2(xr1);
    float4 acc;
    acc.x = f0.x * w0; acc.y = f0.y * w0; acc.z = f1.x * w0; acc.w = f1.y * w0;
    int s = g_rowptr[b][row], e = g_rowptr[b][row + 1];
    int j = s;
    for (; j + 4 <= e; j += 4) {
        int u0 = col[j], u1 = col[j + 1], u2 = col[j + 2], u3 = col[j + 3];
        float wa = dinv[u0] * dv, wb = dinv[u1] * dv;
        float wc = dinv[u2] * dv, wd = dinv[u3] * dv;
        uint2 v0 = __ldg(&x2v[(size_t)u0 * 256 + t]);
        uint2 v1 = __ldg(&x2v[(size_t)u1 * 256 + t]);
        uint2 v2 = __ldg(&x2v[(size_t)u2 * 256 + t]);
        uint2 v3 = __ldg(&x2v[(size_t)u3 * 256 + t]);
        float2 a0 = __half22float2(*(__half2*)&v0.x), a1 = __half22float2(*(__half2*)&v0.y);
        acc.x += a0.x * wa; acc.y += a0.y * wa; acc.z += a1.x * wa; acc.w += a1.y * wa;
        float2 b0 = __half22float2(*(__half2*)&v1.x), b1 = __half22float2(*(__half2*)&v1.y);
        acc.x += b0.x * wb; acc.y += b0.y * wb; acc.z += b1.x * wb; acc.w += b1.y * wb;
        float2 c0 = __half22float2(*(__half2*)&v2.x), c1 = __half22float2(*(__half2*)&v2.y);
        acc.x += c0.x * wc; acc.y += c0.y * wc; acc.z += c1.x * wc; acc.w += c1.y * wc;
        float2 d0 = __half22float2(*(__half2*)&v3.x), d1 = __half22float2(*(__half2*)&v3.y);
        acc.x += d0.x * wd; acc.y += d0.y * wd; acc.z += d1.x * wd; acc.w += d1.y * wd;
    }
    for (; j < e; j++) {
        int u = col[j];
        float w = dinv[u] * dv;
        uint2 xu = __ldg(&x2v[(size_t)u * 256 + t]);
        float2 g0 = __half22float2(*(__half2*)&xu.x), g1 = __half22float2(*(__half2*)&xu.y);
        acc.x += g0.x * w; acc.y += g0.y * w; acc.z += g1.x * w; acc.w += g1.y * w;
    }
    __half2 p0 = __floats2half2_rn(acc.x, acc.y);
    __half2 p1 = __floats2half2_rn(acc.z, acc.w);
    uint2 v;
    v.x = *(uint32_t*)&p0; v.y = *(uint32_t*)&p1;
    ((uint2*)g_a16[b])[(size_t)row * 256 + t] = v;
}

// ---------------- fp16 HMMA GEMM: Y16 = fp16(leaky(A@W + bias)) ----------------
#define BK        64
#define NCHUNK    (F / BK)            // 16
#define ROWPAD    72                   // fp16 elems per smem row (64 data + 8 pad)
#define SA_BYTES  (128 * ROWPAD * 2)   // 18432 per tensor
#define STG_BYTES (2 * SA_BYTES)       // A, W
#define SM_TOT    (2 * STG_BYTES)      // 73728

__global__ __launch_bounds__(256, 2)
void k_tgemm(const float* __restrict__ bias0, const float* __restrict__ bias1, int M) {
    extern __shared__ char smem[];
    uint32_t sb = smem_to_u32(smem);
    int br = blockIdx.z;
    const float* __restrict__ bias = br ? bias1 : bias0;
    const __half* __restrict__ A  = g_a16[br];
    const __half* __restrict__ Wh = g_wh[br];

    int tid = threadIdx.x;
    int wid = tid >> 5, lane = tid & 31;
    int gid = lane >> 2, tig = lane & 3;
    int warp_m = wid & 1, warp_n = wid >> 1;
    int m0 = blockIdx.y * 128;
    int n0 = blockIdx.x * 128;

    float acc[4][4][4];
    #pragma unroll
    for (int i = 0; i < 4; i++)
        #pragma unroll
        for (int j = 0; j < 4; j++)
            #pragma unroll
            for (int q = 0; q < 4; q++) acc[i][j][q] = 0.0f;

    auto load_chunk = [&](int c, int s) {
        uint32_t stg = sb + s * STG_BYTES;
        int k0 = c * BK;
        #pragma unroll
        for (int l = 0; l < 8; l++) {
            int idx = l * 256 + tid;
            int tsr = idx >> 10;          // 0 A, 1 W
            int rem = idx & 1023;
            int row = rem >> 3;
            int c16 = rem & 7;
            const __half* gsrc;
            bool pred = true;
            if (tsr == 0) {
                int grow = m0 + row;
                pred = grow < M;
                gsrc = A + (size_t)(pred ? grow : 0) * F + k0 + c16 * 8;
            } else {
                gsrc = Wh + (size_t)(n0 + row) * F + k0 + c16 * 8;
            }
            uint32_t sdst = stg + tsr * SA_BYTES + row * (ROWPAD * 2) + c16 * 16;
            cp_async16(sdst, gsrc, pred);
        }
        cp_commit();
    };

    load_chunk(0, 0);

    for (int c = 0; c < NCHUNK; c++) {
        int s = c & 1;
        if (c + 1 < NCHUNK) {
            load_chunk(c + 1, s ^ 1);
            cp_wait<1>();
        } else {
            cp_wait<0>();
        }
        __syncthreads();

        uint32_t sa  = sb + s * STG_BYTES;
        uint32_t sbh = sa + SA_BYTES;

        #pragma unroll
        for (int ks = 0; ks < 4; ks++) {
            int kb = ks * 16;
            uint32_t bh[4][2];
            #pragma unroll
            for (int nt = 0; nt < 4; nt++) {
                int n = warp_n * 32 + nt * 8 + gid;
                uint32_t o = n * (ROWPAD * 2) + (kb + tig * 2) * 2;
                bh[nt][0] = lds32(sbh + o);
                bh[nt][1] = lds32(sbh + o + 16);
            }
            #pragma unroll
            for (int mt = 0; mt < 4; mt++) {
                int r = warp_m * 64 + mt * 16 + gid;
                uint32_t o = r * (ROWPAD * 2) + (kb + tig * 2) * 2;
                uint32_t ah[4];
                ah[0] = lds32(sa + o);
                ah[1] = lds32(sa + o + 8 * (ROWPAD * 2));
                ah[2] = lds32(sa + o + 16);
                ah[3] = lds32(sa + o + 8 * (ROWPAD * 2) + 16);
                #pragma unroll
                for (int nt = 0; nt < 4; nt++) {
                    mma16816(acc[mt][nt], ah, bh[nt]);
                }
            }
        }
        __syncthreads();
    }

    __half* __restrict__ Y = g_y16[br];
    #pragma unroll
    for (int mt = 0; mt < 4; mt++) {
        int r0 = m0 + warp_m * 64 + mt * 16 + gid;
        #pragma unroll
        for (int nt = 0; nt < 4; nt++) {
            int col = n0 + warp_n * 32 + nt * 8 + tig * 2;
            float b0 = __ldg(&bias[col]);
            float b1 = __ldg(&bias[col + 1]);
            float* cf = acc[mt][nt];
            if (r0 < M) {
                __half2 v = __floats2half2_rn(leaky(cf[0] + b0), leaky(cf[1] + b1));
                *(__half2*)(Y + (size_t)r0 * F + col) = v;
            }
            if (r0 + 8 < M) {
                __half2 v = __floats2half2_rn(leaky(cf[2] + b0), leaky(cf[3] + b1));
                *(__half2*)(Y + (size_t)(r0 + 8) * F + col) = v;
            }
        }
    }
}

// ---------------- fused pool + fc: one block per (graph, branch) ----------------
__global__ __launch_bounds__(256)
void k_poolfc(const float* __restrict__ Wf0, const float* __restrict__ bf0,
              const float* __restrict__ Wf1, const float* __restrict__ bf1) {
    int b = blockIdx.y;
    int g = blockIdx.x;
    const float* __restrict__ Wf = b ? Wf1 : Wf0;
    const float* __restrict__ bf = b ? bf1 : bf0;
    __shared__ float p[F];
    int t = threadIdx.x;                 // 256
    int s = g_goff[b][g], e = g_goff[b][g + 1];
    const __half2* __restrict__ Y2 = (const __half2*)g_y16[b];
    float2 s0 = {0.f, 0.f}, s1 = {0.f, 0.f};
    for (int r = s; r < e; r++) {
        float2 a = __half22float2(Y2[(size_t)r * 512 + t]);
        float2 c = __half22float2(Y2[(size_t)r * 512 + t + 256]);
        s0.x += a.x; s0.y += a.y; s1.x += c.x; s1.y += c.y;
    }
    float inv = 1.0f / fmaxf((float)(e - s), 1.0f);
    p[2 * t]             = s0.x * inv;
    p[2 * t + 1]         = s0.y * inv;
    p[2 * (t + 256)]     = s1.x * inv;
    p[2 * (t + 256) + 1] = s1.y * inv;
    __syncthreads();
    if (t < DD) {
        float acc = 0.0f;
        #pragma unroll 8
        for (int k = 0; k < F; k++) acc += p[k] * Wf[k * DD + t];
        acc += bf[t];
        g_z[b][g * DD + t] = leaky(acc);
    }
}

// ---------------- final ----------------
__global__ void k_final(const float* __restrict__ fW, const float* __restrict__ fb,
                        float* __restrict__ out) {
    __shared__ float sh[256];
    int g = blockIdx.x, t = threadIdx.x;
    float v;
    if (t < DD) v = g_z[0][g * DD + t] * fW[t];
    else        v = g_z[1][g * DD + (t - DD)] * fW[t];
    sh[t] = v;
    __syncthreads();
    #pragma unroll
    for (int s = 128; s > 0; s >>= 1) {
        if (t < s) sh[t] += sh[t + s];
        __syncthreads();
    }
    if (t == 0) out[g] = sh[0] + fb[0];
}

// ---------------- host launcher ----------------
extern "C" void kernel_launch(void* const* d_in, const int* in_sizes, int n_in,
                              void* d_out, int out_size) {
    const float* x1  = (const float*)d_in[0];
    const void*  ei1 = d_in[1];
    const void*  bt1 = d_in[2];
    const float* x2  = (const float*)d_in[3];
    const void*  ei2 = d_in[4];
    const void*  bt2 = d_in[5];
    int wb = n_in - 10;
    const float* c1W = (const float*)d_in[wb + 0];
    const float* c1b = (const float*)d_in[wb + 1];
    const float* f1W = (const float*)d_in[wb + 2];
    const float* f1b = (const float*)d_in[wb + 3];
    const float* c2W = (const float*)d_in[wb + 4];
    const float* c2b = (const float*)d_in[wb + 5];
    const float* f2W = (const float*)d_in[wb + 6];
    const float* f2b = (const float*)d_in[wb + 7];
    const float* fW  = (const float*)d_in[wb + 8];
    const float* fb  = (const float*)d_in[wb + 9];
    float* out = (float*)d_out;

    int N = in_sizes[0] / F;
    int E = in_sizes[1] / 2;

    cudaFuncSetAttribute(k_tgemm, cudaFuncAttributeMaxDynamicSharedMemorySize, SM_TOT);

    int zb = (2 * MAXN + 255) / 256;
    k_pre<<<4 + zb, 256>>>((const unsigned int*)ei1, (const unsigned int*)bt1,
                           (const unsigned int*)ei2, (const unsigned int*)bt2,
                           2 * E, N, 2 * E, N);
    int nbE = (E + 255) / 256;
    k_deg<<<dim3(nbE, 2), 256>>>(ei1, ei2, E);

    int total4 = N * (F / 4);                      // float4 elems per branch
    int cvb = (2 * total4 + 1023) / 1024;          // convert blocks
    int wtb = (2048 + 3) / 4;                      // 512 transpose blocks
    k_mid<<<2 + cvb + wtb, 1024>>>(x1, x2, c1W, c2W, N, cvb, total4);

    k_fill<<<dim3(nbE + 2, 2), 256>>>(ei1, ei2, bt1, bt2, E, N, nbE);
    k_agg<<<dim3(N, 2), 256>>>();
    k_tgemm<<<dim3(F / 128, (N + 127) / 128, 2), 256, SM_TOT>>>(c1b, c2b, N);
    k_poolfc<<<dim3(NG, 2), 256>>>(f1W, f1b, f2W, f2b);
    k_final<<<NG, 256>>>(fW, fb, out);
}